// round 9
// baseline (speedup 1.0000x reference)
#include <cuda_runtime.h>
#include <cuda_bf16.h>
#include <cstdint>

#define N_NODES   50000
#define N_EDGES   400000
#define E_TOT     (N_EDGES + N_NODES)
#define N_GRAPHS  128
#define D_IN      768
#define D_HID     256
#define NEG_SLOPE 0.2f
#define EPS_COS   1e-8f
#define EPS_BN    1e-5f

#if defined(__CUDA_ARCH_FEAT_SM103_ALL) || defined(__CUDA_ARCH_SPECIFIC__)
#define HAS_TCGEN05 1
#else
#define HAS_TCGEN05 0
#endif

// ---------------- scratch (device globals; no allocation) ----------------
__device__ float    g_rel[N_NODES];
__device__ float    g_bufA[(size_t)N_NODES * D_HID];
__device__ float    g_bufB[(size_t)N_NODES * D_HID];
__device__ float    g_as[N_NODES];
__device__ float    g_ad[N_NODES];
__device__ unsigned g_maxenc[N_NODES];
__device__ float    g_denom[N_NODES];
__device__ unsigned g_maxenc2[N_NODES];
__device__ float    g_denom2[N_NODES];
__device__ float    g_edge[E_TOT];
__device__ float    g_bnsum[D_HID];
__device__ float    g_bnsq[D_HID];
__device__ float    g_bnsc[D_HID];
__device__ float    g_bnsh[D_HID];
__device__ float    g_pool[N_GRAPHS * D_HID];
__device__ int      g_cnt[N_GRAPHS];
// CSR (built once, reused by both layers)
__device__ int      g_dcnt[N_NODES];
__device__ int      g_rowoff[N_NODES + 1];
__device__ int      g_wr[N_NODES];
__device__ int      g_eid[E_TOT];
__device__ int      g_srcid[E_TOT];
// pre-swizzled bf16 hi/lo weight images: [ktile32][256 n-rows][64 bytes] SW64
__device__ unsigned char g_w1h[24 * 16384];
__device__ unsigned char g_w1l[24 * 16384];
__device__ unsigned char g_w2h[8 * 16384];
__device__ unsigned char g_w2l[8 * 16384];

// ---------------- PTX helpers ----------------
__device__ __forceinline__ uint32_t elect_one_pred() {
    uint32_t pred;
    asm volatile(
        "{\n\t.reg .pred p;\n\t"
        "elect.sync _|p, 0xFFFFFFFF;\n\t"
        "selp.b32 %0, 1, 0, p;\n\t}"
        : "=r"(pred));
    return pred;
}
__device__ __forceinline__ uint32_t smem_to_u32(const void* p) {
    uint32_t a;
    asm("{ .reg .u64 t; cvta.to.shared.u64 t, %1; cvt.u32.u64 %0, t; }"
        : "=r"(a) : "l"(p));
    return a;
}
#define MBARRIER_INIT(addr, cnt) \
    asm volatile("mbarrier.init.shared.b64 [%0], %1;" :: "r"((uint32_t)(addr)), "r"((uint32_t)(cnt)) : "memory")
#define MBARRIER_EXPECT_TX(addr, bytes) \
    asm volatile("mbarrier.arrive.expect_tx.shared.b64 _, [%0], %1;" \
        :: "r"((uint32_t)(addr)), "r"((uint32_t)(bytes)) : "memory")
#define MBARRIER_WAIT_PARITY(addr, parity) do { \
    uint32_t _m = (uint32_t)(addr); uint32_t _p = (uint32_t)(parity); uint32_t _d; \
    asm volatile("{\n\t.reg .pred p;\n\t" \
        "mbarrier.try_wait.parity.acquire.cta.shared::cta.b64 p, [%1], %2;\n\t" \
        "selp.b32 %0, 1, 0, p;\n\t}" : "=r"(_d) : "r"(_m), "r"(_p) : "memory"); \
    if (!_d) { \
        asm volatile("{\n\t.reg .pred P1;\n\t" \
            "WL_%=:\n\t" \
            "mbarrier.try_wait.parity.acquire.cta.shared::cta.b64 P1, [%0], %1, 0x989680;\n\t" \
            "@P1 bra.uni WD_%=;\n\t" \
            "bra.uni WL_%=;\n\t" \
            "WD_%=:\n\t}" :: "r"(_m), "r"(_p) : "memory"); \
    } \
} while (0)
#define TCGEN05_ALLOC(sa, n) \
    asm volatile("tcgen05.alloc.cta_group::1.sync.aligned.shared::cta.b32 [%0], %1;" \
        :: "r"((uint32_t)(sa)), "r"((uint32_t)(n)) : "memory")
#define TCGEN05_DEALLOC(t, n) \
    asm volatile("tcgen05.dealloc.cta_group::1.sync.aligned.b32 %0, %1;" :: "r"(t), "r"((uint32_t)(n)))
#define TCGEN05_RELINQ() \
    asm volatile("tcgen05.relinquish_alloc_permit.cta_group::1.sync.aligned;")
#define TCGEN05_COMMIT(mb) \
    asm volatile("tcgen05.commit.cta_group::1.mbarrier::arrive::one.shared::cluster.b64 [%0];" \
        :: "r"((uint32_t)(mb)) : "memory")
#define TCGEN05_FENCE_AFTER()  asm volatile("tcgen05.fence::after_thread_sync;" ::: "memory")
#define TCGEN05_FENCE_BEFORE() asm volatile("tcgen05.fence::before_thread_sync;" ::: "memory")
#define TCGEN05_WAIT_LD()      asm volatile("tcgen05.wait::ld.sync.aligned;" ::: "memory")
#define FENCE_ASYNC_SHARED()   asm volatile("fence.proxy.async.shared::cta;" ::: "memory")
#define TCGEN05_LD_X32(r, ta) \
    asm volatile("tcgen05.ld.sync.aligned.32x32b.x32.b32 " \
        "{%0, %1, %2, %3, %4, %5, %6, %7, %8, %9, %10, %11, %12, %13, %14, %15, " \
        " %16, %17, %18, %19, %20, %21, %22, %23, %24, %25, %26, %27, %28, %29, %30, %31}, [%32];" \
        : "=r"((r)[0]), "=r"((r)[1]), "=r"((r)[2]), "=r"((r)[3]), \
          "=r"((r)[4]), "=r"((r)[5]), "=r"((r)[6]), "=r"((r)[7]), \
          "=r"((r)[8]), "=r"((r)[9]), "=r"((r)[10]), "=r"((r)[11]), \
          "=r"((r)[12]), "=r"((r)[13]), "=r"((r)[14]), "=r"((r)[15]), \
          "=r"((r)[16]), "=r"((r)[17]), "=r"((r)[18]), "=r"((r)[19]), \
          "=r"((r)[20]), "=r"((r)[21]), "=r"((r)[22]), "=r"((r)[23]), \
          "=r"((r)[24]), "=r"((r)[25]), "=r"((r)[26]), "=r"((r)[27]), \
          "=r"((r)[28]), "=r"((r)[29]), "=r"((r)[30]), "=r"((r)[31]) \
        : "r"(ta))

// SW64 K-major descriptor: layout=4, version=1, SBO=32 (512B = 8 rows x 64B), LBO=1
static constexpr uint64_t SMEM_DESC_BASE_SW64K =
    (uint64_t(4) << 61) | (uint64_t(1) << 46) | (uint64_t(32) << 32) | (uint64_t(1) << 16);
__device__ __forceinline__ uint64_t make_desc64(uint32_t addr) {
    return SMEM_DESC_BASE_SW64K | ((uint64_t)(addr >> 4) & 0x3FFF);
}
// idesc: dtype=F32, atype=btype=BF16, N=256, M=128
#define IDESC_G 0x8400490u

#if HAS_TCGEN05
__device__ __forceinline__ void mma_f16_ss(uint32_t d, uint64_t ad, uint64_t bd,
                                           uint32_t idesc, uint32_t en) {
    asm volatile(
        "{\n\t.reg .pred p;\n\t"
        "setp.ne.u32 p, %5, 0;\n\t"
        "tcgen05.mma.cta_group::1.kind::f16 [%0], %1, %2, %3, {%4, %4, %4, %4}, p;\n\t}"
        :: "r"(d), "l"(ad), "l"(bd), "r"(idesc), "r"(0u), "r"(en) : "memory");
}
__device__ __forceinline__ void bulk_cp(uint32_t dst, const void* src, uint32_t bytes,
                                        uint32_t mb) {
    asm volatile(
        "cp.async.bulk.shared::cta.global.mbarrier::complete_tx::bytes [%0], [%1], %2, [%3];"
        :: "r"(dst), "l"(src), "r"(bytes), "r"(mb) : "memory");
}
#endif

__device__ __forceinline__ float warp_red(float v) {
    #pragma unroll
    for (int o = 16; o; o >>= 1) v += __shfl_xor_sync(0xffffffffu, v, o);
    return v;
}
__device__ __forceinline__ unsigned fenc(float f) {
    unsigned u = __float_as_uint(f);
    return (u & 0x80000000u) ? ~u : (u | 0x80000000u);
}
__device__ __forceinline__ float fdec(unsigned u) {
    return (u & 0x80000000u) ? __uint_as_float(u & 0x7FFFFFFFu) : __uint_as_float(~u);
}
__device__ __forceinline__ uint32_t pack_bf(__nv_bfloat16 a, __nv_bfloat16 b) {
    return (uint32_t)__bfloat16_as_ushort(a) | ((uint32_t)__bfloat16_as_ushort(b) << 16);
}

// ---------------- weight prep: fp32 [K,256] -> SW64 bf16 hi/lo, K=32 tiles ----------------
__global__ void k_prep_w(const float* __restrict__ W, int K,
                         unsigned char* __restrict__ hi, unsigned char* __restrict__ lo) {
    int idx = blockIdx.x * blockDim.x + threadIdx.x;
    if (idx >= K * 256) return;
    int k = idx >> 8, n = idx & 255;
    float v = W[idx];
    __nv_bfloat16 h = __float2bfloat16_rn(v);
    __nv_bfloat16 l = __float2bfloat16_rn(v - __bfloat162float(h));
    int kt = k >> 5, kk = k & 31;
    uint32_t off = (uint32_t)(n * 64 + kk * 2);
    off ^= ((off >> 3) & 0x30);
    size_t base = (size_t)kt * 16384 + off;
    *(__nv_bfloat16*)(hi + base) = h;
    *(__nv_bfloat16*)(lo + base) = l;
}

// -------- tcgen05 GEMM: 2-stage K=32 ring, 256 threads, occ=2 ----------
// stage: AH 8K | AL 8K | BH 16K | BL 16K = 48K; 2 stages + ctrl = ~99K
#define SM_TPTR 0
#define SM_MBC0 8
#define SM_MBC1 16
#define SM_MBT0 24
#define SM_MBT1 32
#define SM_ASV  1024
#define SM_ADV  2048
#define SM_STG0 3072
#define STG_SZ  49152
#define OF_AH   0
#define OF_AL   8192
#define OF_BH   16384
#define OF_BL   32768
#define SM_SZ   (SM_STG0 + 2 * STG_SZ)

__global__ __launch_bounds__(256) void k_gemm_tc(
    const float* __restrict__ A, int K,
    const unsigned char* __restrict__ Bh, const unsigned char* __restrict__ Bl,
    float* __restrict__ C,
    const float* __restrict__ rowscale,
    const float* __restrict__ colsc, const float* __restrict__ colsh,
    const float* __restrict__ a_s, const float* __restrict__ a_d,
    float* __restrict__ as_out, float* __restrict__ ad_out, int M)
{
#if HAS_TCGEN05
    extern __shared__ char smem[];
    uint32_t sb = smem_to_u32(smem);
    int tid = threadIdx.x, wid = tid >> 5, lane = tid & 31;
    int m0 = blockIdx.x * 128;

    if (tid == 0) {
        MBARRIER_INIT(sb + SM_MBC0, 1); MBARRIER_INIT(sb + SM_MBC1, 1);
        MBARRIER_INIT(sb + SM_MBT0, 1); MBARRIER_INIT(sb + SM_MBT1, 1);
    }
    if (wid == 0) TCGEN05_ALLOC(sb + SM_TPTR, 256);
    float* sAS = (float*)(smem + SM_ASV);
    float* sAD = (float*)(smem + SM_ADV);
    if (tid < 256) { sAS[tid] = a_s[tid]; sAD[tid] = a_d[tid]; }
    __syncthreads();
    uint32_t tmem;
    asm volatile("ld.shared.b32 %0, [%1];" : "=r"(tmem) : "r"(sb + SM_TPTR));
    if (wid == 0) TCGEN05_RELINQ();

    const int r  = tid >> 1;          // row 0..127
    const int cg = (tid & 1) * 16;    // col group 0 / 16 (fp32 cols in 32-slice)
    const int gr = m0 + r;
    const bool rv = gr < M;
    const float s_row = (rowscale && rv) ? rowscale[gr] : 1.0f;
    const int nk = K >> 5;

    int ph_c[2] = {0, 0};
    int ph_t[2] = {0, 0};

    // prefetch tile 0 into registers
    float4 va[4];
    #pragma unroll
    for (int j = 0; j < 4; j++)
        va[j] = rv ? *(const float4*)(A + (size_t)gr * K + cg + j * 4)
                   : make_float4(0.f, 0.f, 0.f, 0.f);

    for (int kt = 0; kt < nk; kt++) {
        const int s = kt & 1;
        const uint32_t mbc = sb + (s ? SM_MBC1 : SM_MBC0);
        const uint32_t mbt = sb + (s ? SM_MBT1 : SM_MBT0);
        char* stg = smem + SM_STG0 + s * STG_SZ;
        const int k0 = kt << 5;

        // stage s still read by MMA of tile kt-2: wait its commit
        if (kt >= 2) { MBARRIER_WAIT_PARITY(mbc, ph_c[s]); ph_c[s] ^= 1; }

        // kick off B tiles (pre-swizzled SW64 image, 16KB each)
        if (tid == 0) {
            MBARRIER_EXPECT_TX(mbt, 32768u);
            bulk_cp(smem_to_u32(stg + OF_BH), Bh + (size_t)kt * 16384, 16384u, mbt);
            bulk_cp(smem_to_u32(stg + OF_BL), Bl + (size_t)kt * 16384, 16384u, mbt);
        }

        // ---- convert prefetched A regs -> stage s (swizzled bf16 hi/lo) ----
        #pragma unroll
        for (int j = 0; j < 4; j++) {
            float4 v = va[j];
            v.x *= s_row; v.y *= s_row; v.z *= s_row; v.w *= s_row;
            if (colsc) {
                float4 csc = *(const float4*)(colsc + k0 + cg + j * 4);
                float4 csh = *(const float4*)(colsh + k0 + cg + j * 4);
                v.x = fmaxf(v.x * csc.x + csh.x, 0.f);
                v.y = fmaxf(v.y * csc.y + csh.y, 0.f);
                v.z = fmaxf(v.z * csc.z + csh.z, 0.f);
                v.w = fmaxf(v.w * csc.w + csh.w, 0.f);
            }
            __nv_bfloat16 hx = __float2bfloat16_rn(v.x);
            __nv_bfloat16 hy = __float2bfloat16_rn(v.y);
            __nv_bfloat16 hz = __float2bfloat16_rn(v.z);
            __nv_bfloat16 hw = __float2bfloat16_rn(v.w);
            __nv_bfloat16 lx = __float2bfloat16_rn(v.x - __bfloat162float(hx));
            __nv_bfloat16 ly = __float2bfloat16_rn(v.y - __bfloat162float(hy));
            __nv_bfloat16 lz = __float2bfloat16_rn(v.z - __bfloat162float(hz));
            __nv_bfloat16 lw = __float2bfloat16_rn(v.w - __bfloat162float(hw));
            uint2 hv = make_uint2(pack_bf(hx, hy), pack_bf(hz, hw));
            uint2 lv = make_uint2(pack_bf(lx, ly), pack_bf(lz, lw));
            uint32_t off = (uint32_t)(r * 64 + (cg + j * 4) * 2);
            uint32_t so = off ^ ((off >> 3) & 0x30);
            *(uint2*)(stg + OF_AH + so) = hv;
            *(uint2*)(stg + OF_AL + so) = lv;
        }
        // ---- prefetch next A tile (overlaps MMA of this tile) ----
        if (kt + 1 < nk) {
            int k1 = (kt + 1) << 5;
            #pragma unroll
            for (int j = 0; j < 4; j++)
                va[j] = rv ? *(const float4*)(A + (size_t)gr * K + k1 + cg + j * 4)
                           : make_float4(0.f, 0.f, 0.f, 0.f);
        }
        FENCE_ASYNC_SHARED();
        __syncthreads();
        // ---- MMA on stage s (async; next iteration overlaps) ----
        if (wid == 0) {
            MBARRIER_WAIT_PARITY(mbt, ph_t[s]);
            if (elect_one_pred()) {
                uint32_t stb = sb + SM_STG0 + s * STG_SZ;
                uint64_t aH = make_desc64(stb + OF_AH);
                uint64_t aL = make_desc64(stb + OF_AL);
                uint64_t bH = make_desc64(stb + OF_BH);
                uint64_t bL = make_desc64(stb + OF_BL);
                #pragma unroll
                for (int sp = 0; sp < 3; sp++) {
                    uint64_t ad = (sp == 2) ? aL : aH;
                    uint64_t bd = (sp == 1) ? bL : bH;
                    #pragma unroll
                    for (int c = 0; c < 2; c++) {
                        uint32_t en = (kt == 0 && sp == 0 && c == 0) ? 0u : 1u;
                        mma_f16_ss(tmem, ad + c * 2, bd + c * 2, IDESC_G, en);
                    }
                }
                TCGEN05_COMMIT(mbc);
            }
        }
        ph_t[s] ^= 1;
    }
    // drain: wait last tile's commit (in-order queue => all prior done)
    {
        int sl = (nk - 1) & 1;
        MBARRIER_WAIT_PARITY(sb + (sl ? SM_MBC1 : SM_MBC0), ph_c[sl]);
    }
    TCGEN05_FENCE_AFTER();

    // ---- epilogue (warps 0-3): TMEM -> GMEM fp32, fused alpha ----
    if (wid < 4) {
        int row = m0 + wid * 32 + lane;
        float s_acc = 0.f, d_acc = 0.f;
        #pragma unroll
        for (int j = 0; j < 8; j++) {
            uint32_t rg[32];
            TCGEN05_LD_X32(rg, tmem + j * 32);
            TCGEN05_WAIT_LD();
            #pragma unroll
            for (int q = 0; q < 32; q++) {
                float f = __uint_as_float(rg[q]);
                s_acc += f * sAS[j * 32 + q];
                d_acc += f * sAD[j * 32 + q];
            }
            if (row < M) {
                float4* dst = (float4*)(C + (size_t)row * D_HID + j * 32);
                #pragma unroll
                for (int q = 0; q < 8; q++)
                    dst[q] = make_float4(__uint_as_float(rg[q * 4 + 0]), __uint_as_float(rg[q * 4 + 1]),
                                         __uint_as_float(rg[q * 4 + 2]), __uint_as_float(rg[q * 4 + 3]));
            }
        }
        if (row < M) { as_out[row] = s_acc; ad_out[row] = d_acc; }
        TCGEN05_FENCE_BEFORE();
    }
    __syncthreads();
    if (tid == 0) {
        asm volatile("mbarrier.inval.shared.b64 [%0];" :: "r"(sb + SM_MBC0) : "memory");
        asm volatile("mbarrier.inval.shared.b64 [%0];" :: "r"(sb + SM_MBC1) : "memory");
        asm volatile("mbarrier.inval.shared.b64 [%0];" :: "r"(sb + SM_MBT0) : "memory");
        asm volatile("mbarrier.inval.shared.b64 [%0];" :: "r"(sb + SM_MBT1) : "memory");
    }
    __syncthreads();
    if (wid == 0) TCGEN05_DEALLOC(tmem, 256);
#else
    // Correct scalar fallback for the non-arch-specific PTX pass.
    int tid = threadIdx.x;
    if (tid >= 128) return;
    int gr = blockIdx.x * 128 + tid;
    if (gr >= M) return;
    float rs = rowscale ? rowscale[gr] : 1.0f;
    float s_acc = 0.f, d_acc = 0.f;
    for (int n = 0; n < 256; n++) {
        float acc = 0.f;
        for (int k = 0; k < K; k++) {
            int kt = k >> 5, kk = k & 31;
            uint32_t off = (uint32_t)(n * 64 + kk * 2);
            off ^= ((off >> 3) & 0x30);
            float w = __bfloat162float(*(const __nv_bfloat16*)(Bh + (size_t)kt * 16384 + off))
                    + __bfloat162float(*(const __nv_bfloat16*)(Bl + (size_t)kt * 16384 + off));
            float a = A[(size_t)gr * K + k] * rs;
            if (colsc) a = fmaxf(a * colsc[k] + colsh[k], 0.f);
            acc += a * w;
        }
        C[(size_t)gr * 256 + n] = acc;
        s_acc += acc * a_s[n];
        d_acc += acc * a_d[n];
    }
    as_out[gr] = s_acc; ad_out[gr] = d_acc;
#endif
}

// ---------------- zero/init (single launch) ----------------
__global__ void k_zero_all(unsigned* maxenc, float* denom, unsigned* maxenc2, float* denom2,
                           float* bnsum, float* bnsq, float* pool, int* cnt, int* dcnt) {
    int i = blockIdx.x * blockDim.x + threadIdx.x;
    if (i < N_NODES) {
        maxenc[i] = 0u; denom[i] = 0.0f;
        maxenc2[i] = 0u; denom2[i] = 0.0f;
        dcnt[i] = 0;
    }
    if (i < N_GRAPHS * D_HID) pool[i] = 0.0f;
    if (i < D_HID) { bnsum[i] = 0.0f; bnsq[i] = 0.0f; }
    if (i < N_GRAPHS) cnt[i] = 0;
}

// ---------------- CSR build: histogram, scan, fill ----------------
__global__ void k_hist(const int* __restrict__ ei, int* __restrict__ dcnt) {
    int i = blockIdx.x * blockDim.x + threadIdx.x;
    if (i >= E_TOT) return;
    int d = (i < N_EDGES) ? ei[N_EDGES + i] : (i - N_EDGES);
    atomicAdd(&dcnt[d], 1);
}
__global__ __launch_bounds__(1024) void k_scan(const int* __restrict__ dcnt,
                                               int* __restrict__ rowoff,
                                               int* __restrict__ wr) {
    __shared__ int wsum[32];
    int t = threadIdx.x;
    int lane = t & 31, w = t >> 5;
    const int CH = (N_NODES + 1023) / 1024;   // 49
    int lo = t * CH, hi = min(lo + CH, N_NODES);
    int s = 0;
    for (int i = lo; i < hi; i++) s += dcnt[i];
    int inc = s;
    #pragma unroll
    for (int o = 1; o < 32; o <<= 1) {
        int v = __shfl_up_sync(0xffffffffu, inc, o);
        if (lane >= o) inc += v;
    }
    if (lane == 31) wsum[w] = inc;
    __syncthreads();
    if (w == 0) {
        int v = (lane < 32) ? wsum[lane] : 0;
        int wi = v;
        #pragma unroll
        for (int o = 1; o < 32; o <<= 1) {
            int u = __shfl_up_sync(0xffffffffu, wi, o);
            if (lane >= o) wi += u;
        }
        wsum[lane] = wi - v;   // exclusive
        if (lane == 31) rowoff[N_NODES] = wi;
    }
    __syncthreads();
    int run = wsum[w] + inc - s;
    for (int i = lo; i < hi; i++) {
        rowoff[i] = run; wr[i] = run;
        run += dcnt[i];
    }
}
__global__ void k_fill(const int* __restrict__ ei, int* __restrict__ wr,
                       int* __restrict__ eid, int* __restrict__ srcid) {
    int i = blockIdx.x * blockDim.x + threadIdx.x;
    if (i >= E_TOT) return;
    int s, d;
    if (i < N_EDGES) { s = ei[i]; d = ei[N_EDGES + i]; }
    else { s = d = i - N_EDGES; }
    int pos = atomicAdd(&wr[d], 1);
    eid[pos] = i;
    srcid[pos] = s;
}

// ---------------- relevance (cosine, float4) + graph counts ----------------
__global__ void k_rel(const float* __restrict__ claim, const float* __restrict__ x,
                      const int* __restrict__ batch, float* __restrict__ rel,
                      int* __restrict__ cnt) {
    int warp = (blockIdx.x * blockDim.x + threadIdx.x) >> 5;
    int lane = threadIdx.x & 31;
    if (warp >= N_NODES) return;
    int b = batch[warp];
    const float4* ce = (const float4*)(claim + (size_t)b * D_IN);
    const float4* xv = (const float4*)(x + (size_t)warp * D_IN);
    float dot = 0.f, nc = 0.f, nx = 0.f;
    #pragma unroll
    for (int k = lane; k < D_IN / 4; k += 32) {
        float4 c = ce[k], v = xv[k];
        dot += c.x * v.x + c.y * v.y + c.z * v.z + c.w * v.w;
        nc  += c.x * c.x + c.y * c.y + c.z * c.z + c.w * c.w;
        nx  += v.x * v.x + v.y * v.y + v.z * v.z + v.w * v.w;
    }
    dot = warp_red(dot); nc = warp_red(nc); nx = warp_red(nx);
    if (lane == 0) {
        float nrm = sqrtf(nc) * sqrtf(nx);
        rel[warp] = dot / fmaxf(nrm, EPS_COS);
        atomicAdd(&cnt[b], 1);
    }
}

// ---------------- edge pass 1: leaky-relu score + segment max ----------------
__global__ void k_edge_max(const int* __restrict__ ei,
                           const float* __restrict__ as, const float* __restrict__ ad,
                           float* __restrict__ edge, unsigned* __restrict__ maxenc) {
    int i = blockIdx.x * blockDim.x + threadIdx.x;
    if (i >= E_TOT) return;
    int s, d;
    if (i < N_EDGES) { s = ei[i]; d = ei[N_EDGES + i]; }
    else { s = d = i - N_EDGES; }
    float e = as[s] + ad[d];
    e = (e > 0.f) ? e : NEG_SLOPE * e;
    edge[i] = e;
    atomicMax(&maxenc[d], fenc(e));
}

// ---------------- edge pass 2: exp + segment sum ----------------
__global__ void k_edge_exp(const int* __restrict__ ei,
                           float* __restrict__ edge,
                           const unsigned* __restrict__ maxenc,
                           float* __restrict__ denom) {
    int i = blockIdx.x * blockDim.x + threadIdx.x;
    if (i >= E_TOT) return;
    int d = (i < N_EDGES) ? ei[N_EDGES + i] : (i - N_EDGES);
    float ex = expf(edge[i] - fdec(maxenc[d]));
    edge[i] = ex;
    atomicAdd(&denom[d], ex);
}

// ------- edge pass 3 (layer 1): CSR aggregation, warp per dst -------
__global__ void k_agg_csr(const float* __restrict__ h, float* __restrict__ agg,
                          const int* __restrict__ rowoff, const int* __restrict__ eid,
                          const int* __restrict__ srcid,
                          const float* __restrict__ edge,
                          const float* __restrict__ denom) {
    int d = (int)(((size_t)blockIdx.x * blockDim.x + threadIdx.x) >> 5);
    int lane = threadIdx.x & 31;
    if (d >= N_NODES) return;
    int beg = rowoff[d], end = rowoff[d + 1];
    float invden = __frcp_rn(denom[d]);
    float4 a0 = make_float4(0.f, 0.f, 0.f, 0.f);
    float4 a1 = make_float4(0.f, 0.f, 0.f, 0.f);
    for (int i = beg; i < end; i++) {
        int e = eid[i];
        int s = srcid[i];
        float attn = edge[e] * invden;
        const float4* hs = (const float4*)(h + (size_t)s * D_HID);
        float4 v0 = hs[lane], v1 = hs[lane + 32];
        a0.x += attn * v0.x; a0.y += attn * v0.y; a0.z += attn * v0.z; a0.w += attn * v0.w;
        a1.x += attn * v1.x; a1.y += attn * v1.y; a1.z += attn * v1.z; a1.w += attn * v1.w;
    }
    float4* od = (float4*)(agg + (size_t)d * D_HID);
    od[lane] = a0;
    od[lane + 32] = a1;
}

// ------- edge pass 3 (layer 2): CSR agg + fused relu(+b2) + mean-pool -------
__global__ void k_agg_pool(const float* __restrict__ h,
                           const int* __restrict__ rowoff, const int* __restrict__ eid,
                           const int* __restrict__ srcid,
                           const float* __restrict__ edge,
                           const float* __restrict__ denom,
                           const float* __restrict__ b2,
                           const int* __restrict__ batch,
                           float* __restrict__ pool) {
    int d = (int)(((size_t)blockIdx.x * blockDim.x + threadIdx.x) >> 5);
    int lane = threadIdx.x & 31;
    if (d >= N_NODES) return;
    int beg = rowoff[d], end = rowoff[d + 1];
    float invden = __frcp_rn(denom[d]);
    float4 a0 = make_float4(0.f, 0.f, 0.f, 0.f);
    float4 a1 = make_float4(0.f, 0.f, 0.f, 0.f);
    for (int i = beg; i < end; i++) {
        int e = eid[i];
        int s = srcid[i];
        float attn = edge[e] * invden;
        const float4* hs = (const float4*)(h + (size_t)s * D_HID);
        float4 v0 = hs[lane], v1 = hs[lane + 32];
        a0.x += attn * v0.x; a0.y += attn * v0.y; a0.z += attn * v0.z; a0.w += attn * v0.w;
        a1.x += attn * v1.x; a1.y += attn * v1.y; a1.z += attn * v1.z; a1.w += attn * v1.w;
    }
    float4 b0 = ((const float4*)b2)[lane];
    float4 b1 = ((const float4*)b2)[lane + 32];
    a0.x = fmaxf(a0.x + b0.x, 0.f); a0.y = fmaxf(a0.y + b0.y, 0.f);
    a0.z = fmaxf(a0.z + b0.z, 0.f); a0.w = fmaxf(a0.w + b0.w, 0.f);
    a1.x = fmaxf(a1.x + b1.x, 0.f); a1.y = fmaxf(a1.y + b1.y, 0.f);
    a1.z = fmaxf(a1.z + b1.z, 0.f); a1.w = fmaxf(a1.w + b1.w, 0.f);
    int g = batch[d];
    float4* pg = (float4*)(pool + (size_t)g * D_HID);
    asm volatile("red.global.add.v4.f32 [%0], {%1,%2,%3,%4};"
                 :: "l"(pg + lane), "f"(a0.x), "f"(a0.y), "f"(a0.z), "f"(a0.w) : "memory");
    asm volatile("red.global.add.v4.f32 [%0], {%1,%2,%3,%4};"
                 :: "l"(pg + lane + 32), "f"(a1.x), "f"(a1.y), "f"(a1.z), "f"(a1.w) : "memory");
}

// ---------------- BatchNorm stats ----------------
#define ROWS_PER_BLK 64
__global__ void k_bnstats(const float* __restrict__ h, float* __restrict__ bsum,
                          float* __restrict__ bsq) {
    int col = threadIdx.x;
    int r0 = blockIdx.x * ROWS_PER_BLK;
    int r1 = min(r0 + ROWS_PER_BLK, N_NODES);
    float s = 0.f, q = 0.f;
    for (int r = r0; r < r1; r++) {
        float v = h[(size_t)r * D_HID + col];
        s += v; q += v * v;
    }
    atomicAdd(&bsum[col], s);
    atomicAdd(&bsq[col], q);
}

// ---------------- BN finalize: per-column scale/shift ----------------
__global__ void k_bnfin(const float* __restrict__ bsum, const float* __restrict__ bsq,
                        const float* __restrict__ gamma, const float* __restrict__ beta,
                        float* __restrict__ sc, float* __restrict__ sh) {
    int col = threadIdx.x;
    float mu = bsum[col] * (1.0f / N_NODES);
    float var = bsq[col] * (1.0f / N_NODES) - mu * mu;
    float s = gamma[col] * rsqrtf(var + EPS_BN);
    sc[col] = s;
    sh[col] = beta[col] - mu * s;
}

// ---------------- classifier ----------------
__global__ void k_clf(const float* __restrict__ pool, const int* __restrict__ cnt,
                      const float* __restrict__ claim, const float* __restrict__ W,
                      const float* __restrict__ bias, float* __restrict__ out) {
    __shared__ float red[256];
    int b = blockIdx.x;
    int t = threadIdx.x;
    float c = fmaxf((float)cnt[b], 1.0f);
    float part = (pool[b * D_HID + t] / c) * W[t];
    #pragma unroll
    for (int j = 0; j < 3; j++) {
        int k = t + j * 256;
        part += claim[(size_t)b * D_IN + k] * W[D_HID + k];
    }
    red[t] = part;
    __syncthreads();
    #pragma unroll
    for (int o = 128; o; o >>= 1) {
        if (t < o) red[t] += red[t + o];
        __syncthreads();
    }
    if (t == 0) out[b] = red[0] + bias[0];
}

// ---------------- host launcher ----------------
extern "C" void kernel_launch(void* const* d_in, const int* in_sizes, int n_in,
                              void* d_out, int out_size) {
    const float* claim   = (const float*)d_in[0];
    const float* x       = (const float*)d_in[1];
    const int*   ei      = (const int*)d_in[2];
    const int*   batch   = (const int*)d_in[3];
    const float* W1      = (const float*)d_in[4];
    const float* a_src1  = (const float*)d_in[5];
    const float* a_dst1  = (const float*)d_in[6];
    // d_in[7] = b1 : provably no-op through training-mode BatchNorm
    const float* W2      = (const float*)d_in[8];
    const float* a_src2  = (const float*)d_in[9];
    const float* a_dst2  = (const float*)d_in[10];
    const float* b2      = (const float*)d_in[11];
    const float* gamma   = (const float*)d_in[12];
    const float* beta    = (const float*)d_in[13];
    const float* clfW    = (const float*)d_in[14];
    const float* clfb    = (const float*)d_in[15];
    float* out = (float*)d_out;

    float *p_rel, *p_A, *p_B, *p_as, *p_ad, *p_denom, *p_denom2, *p_edge,
          *p_bnsum, *p_bnsq, *p_bnsc, *p_bnsh, *p_pool;
    unsigned *p_maxenc, *p_maxenc2;
    int *p_cnt, *p_dcnt, *p_rowoff, *p_wr, *p_eid, *p_srcid;
    unsigned char *p_w1h, *p_w1l, *p_w2h, *p_w2l;
    cudaGetSymbolAddress((void**)&p_rel, g_rel);
    cudaGetSymbolAddress((void**)&p_A, g_bufA);
    cudaGetSymbolAddress((void**)&p_B, g_bufB);
    cudaGetSymbolAddress((void**)&p_as, g_as);
    cudaGetSymbolAddress((void**)&p_ad, g_ad);
    cudaGetSymbolAddress((void**)&p_maxenc, g_maxenc);
    cudaGetSymbolAddress((void**)&p_denom, g_denom);
    cudaGetSymbolAddress((void**)&p_maxenc2, g_maxenc2);
    cudaGetSymbolAddress((void**)&p_denom2, g_denom2);
    cudaGetSymbolAddress((void**)&p_edge, g_edge);
    cudaGetSymbolAddress((void**)&p_bnsum, g_bnsum);
    cudaGetSymbolAddress((void**)&p_bnsq, g_bnsq);
    cudaGetSymbolAddress((void**)&p_bnsc, g_bnsc);
    cudaGetSymbolAddress((void**)&p_bnsh, g_bnsh);
    cudaGetSymbolAddress((void**)&p_pool, g_pool);
    cudaGetSymbolAddress((void**)&p_cnt, g_cnt);
    cudaGetSymbolAddress((void**)&p_dcnt, g_dcnt);
    cudaGetSymbolAddress((void**)&p_rowoff, g_rowoff);
    cudaGetSymbolAddress((void**)&p_wr, g_wr);
    cudaGetSymbolAddress((void**)&p_eid, g_eid);
    cudaGetSymbolAddress((void**)&p_srcid, g_srcid);
    cudaGetSymbolAddress((void**)&p_w1h, g_w1h);
    cudaGetSymbolAddress((void**)&p_w1l, g_w1l);
    cudaGetSymbolAddress((void**)&p_w2h, g_w2h);
    cudaGetSymbolAddress((void**)&p_w2l, g_w2l);

    cudaFuncSetAttribute(k_gemm_tc, cudaFuncAttributeMaxDynamicSharedMemorySize, SM_SZ);

    const int nodeBlocks = (N_NODES + 255) / 256;
    const int edgeBlocks = (E_TOT + 255) / 256;
    const int warpNodeBlocks = (N_NODES * 32 + 255) / 256;
    const int chunkBlocks = (N_NODES + ROWS_PER_BLK - 1) / ROWS_PER_BLK;
    const int gemmBlocks = (N_NODES + 127) / 128;

    // launch order: GEMM1 stays the 4th launch (ncu captures #4).
    k_zero_all<<<nodeBlocks, 256>>>(p_maxenc, p_denom, p_maxenc2, p_denom2,
                                    p_bnsum, p_bnsq, p_pool, p_cnt, p_dcnt);
    k_rel<<<warpNodeBlocks, 256>>>(claim, x, batch, p_rel, p_cnt);
    k_prep_w<<<(D_IN * 256 + 255) / 256, 256>>>(W1, D_IN, p_w1h, p_w1l);
    k_gemm_tc<<<gemmBlocks, 256, SM_SZ>>>(x, D_IN, p_w1h, p_w1l, p_A,
                                          p_rel, nullptr, nullptr,
                                          a_src1, a_dst1, p_as, p_ad, N_NODES);
    k_prep_w<<<(D_HID * 256 + 255) / 256, 256>>>(W2, D_HID, p_w2h, p_w2l);
    k_hist<<<edgeBlocks, 256>>>(ei, p_dcnt);
    k_scan<<<1, 1024>>>(p_dcnt, p_rowoff, p_wr);
    k_fill<<<edgeBlocks, 256>>>(ei, p_wr, p_eid, p_srcid);

    // ---- layer 1 edge phase ----
    k_edge_max<<<edgeBlocks, 256>>>(ei, p_as, p_ad, p_edge, p_maxenc);
    k_edge_exp<<<edgeBlocks, 256>>>(ei, p_edge, p_maxenc, p_denom);
    k_agg_csr<<<warpNodeBlocks, 256>>>(p_A, p_B, p_rowoff, p_eid, p_srcid, p_edge, p_denom);

    // ---- BN stats + finalize (apply fused into GEMM2's A-loader) ----
    k_bnstats<<<chunkBlocks, 256>>>(p_B, p_bnsum, p_bnsq);
    k_bnfin<<<1, 256>>>(p_bnsum, p_bnsq, gamma, beta, p_bnsc, p_bnsh);

    // ---- layer 2: GEMM (BN+ReLU fused) + edge phase + fused pooling ----
    k_gemm_tc<<<gemmBlocks, 256, SM_SZ>>>(p_B, D_HID, p_w2h, p_w2l, p_A,
                                          nullptr, p_bnsc, p_bnsh,
                                          a_src2, a_dst2, p_as, p_ad, N_NODES);
    k_edge_max<<<edgeBlocks, 256>>>(ei, p_as, p_ad, p_edge, p_maxenc2);
    k_edge_exp<<<edgeBlocks, 256>>>(ei, p_edge, p_maxenc2, p_denom2);
    k_agg_pool<<<warpNodeBlocks, 256>>>(p_A, p_rowoff, p_eid, p_srcid, p_edge, p_denom2,
                                        b2, batch, p_pool);

    // ---- classifier ----
    k_clf<<<N_GRAPHS, 256>>>(p_pool, p_cnt, claim, clfW, clfb, out);
}

// round 10
// speedup vs baseline: 1.1958x; 1.1958x over previous
#include <cuda_runtime.h>
#include <cuda_bf16.h>
#include <cstdint>

#define N_NODES   50000
#define N_EDGES   400000
#define E_TOT     (N_EDGES + N_NODES)
#define N_GRAPHS  128
#define D_IN      768
#define D_HID     256
#define NEG_SLOPE 0.2f
#define EPS_COS   1e-8f
#define EPS_BN    1e-5f

#if defined(__CUDA_ARCH_FEAT_SM103_ALL) || defined(__CUDA_ARCH_SPECIFIC__)
#define HAS_TCGEN05 1
#else
#define HAS_TCGEN05 0
#endif

// ---------------- scratch (device globals; no allocation) ----------------
__device__ float    g_rel[N_NODES];
__device__ float    g_bufA[(size_t)N_NODES * D_HID];
__device__ float    g_bufB[(size_t)N_NODES * D_HID];
__device__ float    g_as[N_NODES];
__device__ float    g_ad[N_NODES];
__device__ float    g_bnsum[D_HID];
__device__ float    g_bnsq[D_HID];
__device__ float    g_bnsc[D_HID];
__device__ float    g_bnsh[D_HID];
__device__ float    g_pool[N_GRAPHS * D_HID];
__device__ int      g_cnt[N_GRAPHS];
// CSR (built once, reused by both layers)
__device__ int      g_dcnt[N_NODES];
__device__ int      g_rowoff[N_NODES + 1];
__device__ int      g_wr[N_NODES];
__device__ int      g_srcid[E_TOT];
// pre-swizzled bf16 hi/lo weight images: [ktile64][256 n-rows][128 bytes] SW128
__device__ unsigned char g_w1h[12 * 32768];
__device__ unsigned char g_w1l[12 * 32768];
__device__ unsigned char g_w2h[4 * 32768];
__device__ unsigned char g_w2l[4 * 32768];

// ---------------- PTX helpers ----------------
__device__ __forceinline__ uint32_t elect_one_pred() {
    uint32_t pred;
    asm volatile(
        "{\n\t.reg .pred p;\n\t"
        "elect.sync _|p, 0xFFFFFFFF;\n\t"
        "selp.b32 %0, 1, 0, p;\n\t}"
        : "=r"(pred));
    return pred;
}
__device__ __forceinline__ uint32_t smem_to_u32(const void* p) {
    uint32_t a;
    asm("{ .reg .u64 t; cvta.to.shared.u64 t, %1; cvt.u32.u64 %0, t; }"
        : "=r"(a) : "l"(p));
    return a;
}
#define MBARRIER_INIT(addr, cnt) \
    asm volatile("mbarrier.init.shared.b64 [%0], %1;" :: "r"((uint32_t)(addr)), "r"((uint32_t)(cnt)) : "memory")
#define MBARRIER_EXPECT_TX(addr, bytes) \
    asm volatile("mbarrier.arrive.expect_tx.shared.b64 _, [%0], %1;" \
        :: "r"((uint32_t)(addr)), "r"((uint32_t)(bytes)) : "memory")
#define MBARRIER_WAIT_PARITY(addr, parity) do { \
    uint32_t _m = (uint32_t)(addr); uint32_t _p = (uint32_t)(parity); uint32_t _d; \
    asm volatile("{\n\t.reg .pred p;\n\t" \
        "mbarrier.try_wait.parity.acquire.cta.shared::cta.b64 p, [%1], %2;\n\t" \
        "selp.b32 %0, 1, 0, p;\n\t}" : "=r"(_d) : "r"(_m), "r"(_p) : "memory"); \
    if (!_d) { \
        asm volatile("{\n\t.reg .pred P1;\n\t" \
            "WL_%=:\n\t" \
            "mbarrier.try_wait.parity.acquire.cta.shared::cta.b64 P1, [%0], %1, 0x989680;\n\t" \
            "@P1 bra.uni WD_%=;\n\t" \
            "bra.uni WL_%=;\n\t" \
            "WD_%=:\n\t}" :: "r"(_m), "r"(_p) : "memory"); \
    } \
} while (0)
#define TCGEN05_ALLOC(sa, n) \
    asm volatile("tcgen05.alloc.cta_group::1.sync.aligned.shared::cta.b32 [%0], %1;" \
        :: "r"((uint32_t)(sa)), "r"((uint32_t)(n)) : "memory")
#define TCGEN05_DEALLOC(t, n) \
    asm volatile("tcgen05.dealloc.cta_group::1.sync.aligned.b32 %0, %1;" :: "r"(t), "r"((uint32_t)(n)))
#define TCGEN05_RELINQ() \
    asm volatile("tcgen05.relinquish_alloc_permit.cta_group::1.sync.aligned;")
#define TCGEN05_COMMIT(mb) \
    asm volatile("tcgen05.commit.cta_group::1.mbarrier::arrive::one.shared::cluster.b64 [%0];" \
        :: "r"((uint32_t)(mb)) : "memory")
#define TCGEN05_FENCE_AFTER()  asm volatile("tcgen05.fence::after_thread_sync;" ::: "memory")
#define TCGEN05_FENCE_BEFORE() asm volatile("tcgen05.fence::before_thread_sync;" ::: "memory")
#define TCGEN05_WAIT_LD()      asm volatile("tcgen05.wait::ld.sync.aligned;" ::: "memory")
#define FENCE_ASYNC_SHARED()   asm volatile("fence.proxy.async.shared::cta;" ::: "memory")
#define TCGEN05_LD_X32(r, ta) \
    asm volatile("tcgen05.ld.sync.aligned.32x32b.x32.b32 " \
        "{%0, %1, %2, %3, %4, %5, %6, %7, %8, %9, %10, %11, %12, %13, %14, %15, " \
        " %16, %17, %18, %19, %20, %21, %22, %23, %24, %25, %26, %27, %28, %29, %30, %31}, [%32];" \
        : "=r"((r)[0]), "=r"((r)[1]), "=r"((r)[2]), "=r"((r)[3]), \
          "=r"((r)[4]), "=r"((r)[5]), "=r"((r)[6]), "=r"((r)[7]), \
          "=r"((r)[8]), "=r"((r)[9]), "=r"((r)[10]), "=r"((r)[11]), \
          "=r"((r)[12]), "=r"((r)[13]), "=r"((r)[14]), "=r"((r)[15]), \
          "=r"((r)[16]), "=r"((r)[17]), "=r"((r)[18]), "=r"((r)[19]), \
          "=r"((r)[20]), "=r"((r)[21]), "=r"((r)[22]), "=r"((r)[23]), \
          "=r"((r)[24]), "=r"((r)[25]), "=r"((r)[26]), "=r"((r)[27]), \
          "=r"((r)[28]), "=r"((r)[29]), "=r"((r)[30]), "=r"((r)[31]) \
        : "r"(ta))

static constexpr uint64_t SMEM_DESC_BASE_SW128 =
    (uint64_t(2) << 61) | (uint64_t(1) << 46) | (uint64_t(64) << 32) | (uint64_t(1) << 16);
__device__ __forceinline__ uint64_t make_desc(uint32_t addr) {
    return SMEM_DESC_BASE_SW128 | ((uint64_t)(addr >> 4) & 0x3FFF);
}
// idesc: dtype=F32, atype=btype=BF16, N=256, M=128
#define IDESC_G 0x8400490u

#if HAS_TCGEN05
__device__ __forceinline__ void mma_f16_ss(uint32_t d, uint64_t ad, uint64_t bd,
                                           uint32_t idesc, uint32_t en) {
    asm volatile(
        "{\n\t.reg .pred p;\n\t"
        "setp.ne.u32 p, %5, 0;\n\t"
        "tcgen05.mma.cta_group::1.kind::f16 [%0], %1, %2, %3, {%4, %4, %4, %4}, p;\n\t}"
        :: "r"(d), "l"(ad), "l"(bd), "r"(idesc), "r"(0u), "r"(en) : "memory");
}
__device__ __forceinline__ void bulk_cp(uint32_t dst, const void* src, uint32_t bytes,
                                        uint32_t mb) {
    asm volatile(
        "cp.async.bulk.shared::cta.global.mbarrier::complete_tx::bytes [%0], [%1], %2, [%3];"
        :: "r"(dst), "l"(src), "r"(bytes), "r"(mb) : "memory");
}
#endif

__device__ __forceinline__ float warp_red(float v) {
    #pragma unroll
    for (int o = 16; o; o >>= 1) v += __shfl_xor_sync(0xffffffffu, v, o);
    return v;
}
__device__ __forceinline__ uint32_t pack_bf(__nv_bfloat16 a, __nv_bfloat16 b) {
    return (uint32_t)__bfloat16_as_ushort(a) | ((uint32_t)__bfloat16_as_ushort(b) << 16);
}

// ---------------- weight prep: fp32 [K,256] -> SW128 bf16 hi/lo, K=64 tiles ----------------
__global__ void k_prep_w(const float* __restrict__ W, int K,
                         unsigned char* __restrict__ hi, unsigned char* __restrict__ lo) {
    int idx = blockIdx.x * blockDim.x + threadIdx.x;
    if (idx >= K * 256) return;
    int k = idx >> 8, n = idx & 255;
    float v = W[idx];
    __nv_bfloat16 h = __float2bfloat16_rn(v);
    __nv_bfloat16 l = __float2bfloat16_rn(v - __bfloat162float(h));
    int kt = k >> 6, kk = k & 63;
    uint32_t off = (uint32_t)(n * 128 + kk * 2);
    off ^= ((off >> 3) & 0x70);
    size_t base = (size_t)kt * 32768 + off;
    *(__nv_bfloat16*)(hi + base) = h;
    *(__nv_bfloat16*)(lo + base) = l;
}

// -------- tcgen05 GEMM (R8 config: K=64 single stage, 256 thr, occ=2) ----
#define SM_TPTR 0
#define SM_MBAR 8
#define SM_MBT  16
#define SM_ASV  1024
#define SM_ADV  2048
#define SM_AH   3072
#define SM_AL   (SM_AH + 16384)
#define SM_BH   (SM_AL + 16384)
#define SM_BL   (SM_BH + 32768)
#define SM_SZ   (SM_BL + 32768)

__global__ __launch_bounds__(256) void k_gemm_tc(
    const float* __restrict__ A, int K,
    const unsigned char* __restrict__ Bh, const unsigned char* __restrict__ Bl,
    float* __restrict__ C,
    const float* __restrict__ rowscale,
    const float* __restrict__ colsc, const float* __restrict__ colsh,
    const float* __restrict__ a_s, const float* __restrict__ a_d,
    float* __restrict__ as_out, float* __restrict__ ad_out, int M)
{
#if HAS_TCGEN05
    extern __shared__ char smem[];
    uint32_t sb = smem_to_u32(smem);
    int tid = threadIdx.x, wid = tid >> 5, lane = tid & 31;
    int m0 = blockIdx.x * 128;

    if (tid == 0) { MBARRIER_INIT(sb + SM_MBAR, 1); MBARRIER_INIT(sb + SM_MBT, 1); }
    if (wid == 0) TCGEN05_ALLOC(sb + SM_TPTR, 256);
    float* sAS = (float*)(smem + SM_ASV);
    float* sAD = (float*)(smem + SM_ADV);
    if (tid < 256) { sAS[tid] = a_s[tid]; sAD[tid] = a_d[tid]; }
    __syncthreads();
    uint32_t tmem;
    asm volatile("ld.shared.b32 %0, [%1];" : "=r"(tmem) : "r"(sb + SM_TPTR));
    if (wid == 0) TCGEN05_RELINQ();

    const uint64_t aH = make_desc(sb + SM_AH);
    const uint64_t aL = make_desc(sb + SM_AL);
    const uint64_t bH = make_desc(sb + SM_BH);
    const uint64_t bL = make_desc(sb + SM_BL);

    int rbase = tid >> 4;        // 0..15
    int cq = (tid & 15) << 2;    // 0,4,...,60
    int ph = 0, ph_t = 0;
    const int nk = K >> 6;

    float s_row[8];
    #pragma unroll
    for (int i = 0; i < 8; i++) {
        int gr = m0 + i * 16 + rbase;
        s_row[i] = (rowscale && gr < M) ? rowscale[gr] : 1.0f;
    }

    float4 va[8];
    #pragma unroll
    for (int i = 0; i < 8; i++) {
        int gr = m0 + i * 16 + rbase;
        va[i] = (gr < M) ? *(const float4*)(A + (size_t)gr * K + cq)
                         : make_float4(0.f, 0.f, 0.f, 0.f);
    }

    for (int kt = 0; kt < nk; kt++) {
        if (kt) { MBARRIER_WAIT_PARITY(sb + SM_MBAR, ph); ph ^= 1; }
        int k0 = kt << 6;

        if (tid == 0) {
            MBARRIER_EXPECT_TX(sb + SM_MBT, 65536u);
            bulk_cp(sb + SM_BH, Bh + (size_t)kt * 32768, 32768u, sb + SM_MBT);
            bulk_cp(sb + SM_BL, Bl + (size_t)kt * 32768, 32768u, sb + SM_MBT);
        }

        float4 csc = make_float4(1.f, 1.f, 1.f, 1.f);
        float4 csh = make_float4(0.f, 0.f, 0.f, 0.f);
        if (colsc) {
            csc = *(const float4*)(colsc + k0 + cq);
            csh = *(const float4*)(colsh + k0 + cq);
        }
        #pragma unroll
        for (int i = 0; i < 8; i++) {
            int r = i * 16 + rbase;
            float4 v = va[i];
            float sc = s_row[i];
            v.x *= sc; v.y *= sc; v.z *= sc; v.w *= sc;
            if (colsc) {
                v.x = fmaxf(v.x * csc.x + csh.x, 0.f);
                v.y = fmaxf(v.y * csc.y + csh.y, 0.f);
                v.z = fmaxf(v.z * csc.z + csh.z, 0.f);
                v.w = fmaxf(v.w * csc.w + csh.w, 0.f);
            }
            __nv_bfloat16 hx = __float2bfloat16_rn(v.x);
            __nv_bfloat16 hy = __float2bfloat16_rn(v.y);
            __nv_bfloat16 hz = __float2bfloat16_rn(v.z);
            __nv_bfloat16 hw = __float2bfloat16_rn(v.w);
            __nv_bfloat16 lx = __float2bfloat16_rn(v.x - __bfloat162float(hx));
            __nv_bfloat16 ly = __float2bfloat16_rn(v.y - __bfloat162float(hy));
            __nv_bfloat16 lz = __float2bfloat16_rn(v.z - __bfloat162float(hz));
            __nv_bfloat16 lw = __float2bfloat16_rn(v.w - __bfloat162float(hw));
            uint2 hv = make_uint2(pack_bf(hx, hy), pack_bf(hz, hw));
            uint2 lv = make_uint2(pack_bf(lx, ly), pack_bf(lz, lw));
            uint32_t off = (uint32_t)(r * 128 + cq * 2);
            uint32_t so = off ^ ((off >> 3) & 0x70);
            *(uint2*)(smem + SM_AH + so) = hv;
            *(uint2*)(smem + SM_AL + so) = lv;
        }
        if (kt + 1 < nk) {
            int k1 = (kt + 1) << 6;
            #pragma unroll
            for (int i = 0; i < 8; i++) {
                int gr = m0 + i * 16 + rbase;
                va[i] = (gr < M) ? *(const float4*)(A + (size_t)gr * K + k1 + cq)
                                 : make_float4(0.f, 0.f, 0.f, 0.f);
            }
        }
        FENCE_ASYNC_SHARED();
        __syncthreads();
        if (wid == 0) {
            MBARRIER_WAIT_PARITY(sb + SM_MBT, ph_t);
            if (elect_one_pred()) {
                #pragma unroll
                for (int sp = 0; sp < 3; sp++) {
                    uint64_t ad = (sp == 2) ? aL : aH;
                    uint64_t bd = (sp == 1) ? bL : bH;
                    #pragma unroll
                    for (int c = 0; c < 4; c++) {
                        uint32_t en = (kt == 0 && sp == 0 && c == 0) ? 0u : 1u;
                        mma_f16_ss(tmem, ad + c * 2, bd + c * 2, IDESC_G, en);
                    }
                }
                TCGEN05_COMMIT(sb + SM_MBAR);
            }
        }
        ph_t ^= 1;
    }
    MBARRIER_WAIT_PARITY(sb + SM_MBAR, ph);
    TCGEN05_FENCE_AFTER();

    if (wid < 4) {
        int row = m0 + wid * 32 + lane;
        float s_acc = 0.f, d_acc = 0.f;
        #pragma unroll
        for (int j = 0; j < 8; j++) {
            uint32_t r[32];
            TCGEN05_LD_X32(r, tmem + j * 32);
            TCGEN05_WAIT_LD();
            #pragma unroll
            for (int q = 0; q < 32; q++) {
                float f = __uint_as_float(r[q]);
                s_acc += f * sAS[j * 32 + q];
                d_acc += f * sAD[j * 32 + q];
            }
            if (row < M) {
                float4* dst = (float4*)(C + (size_t)row * D_HID + j * 32);
                #pragma unroll
                for (int q = 0; q < 8; q++)
                    dst[q] = make_float4(__uint_as_float(r[q * 4 + 0]), __uint_as_float(r[q * 4 + 1]),
                                         __uint_as_float(r[q * 4 + 2]), __uint_as_float(r[q * 4 + 3]));
            }
        }
        if (row < M) { as_out[row] = s_acc; ad_out[row] = d_acc; }
        TCGEN05_FENCE_BEFORE();
    }
    __syncthreads();
    if (tid == 0) {
        asm volatile("mbarrier.inval.shared.b64 [%0];" :: "r"(sb + SM_MBAR) : "memory");
        asm volatile("mbarrier.inval.shared.b64 [%0];" :: "r"(sb + SM_MBT) : "memory");
    }
    __syncthreads();
    if (wid == 0) TCGEN05_DEALLOC(tmem, 256);
#else
    // Correct scalar fallback for the non-arch-specific PTX pass.
    int tid = threadIdx.x;
    if (tid >= 128) return;
    int gr = blockIdx.x * 128 + tid;
    if (gr >= M) return;
    float rs = rowscale ? rowscale[gr] : 1.0f;
    float s_acc = 0.f, d_acc = 0.f;
    for (int n = 0; n < 256; n++) {
        float acc = 0.f;
        for (int k = 0; k < K; k++) {
            int kt = k >> 6, kk = k & 63;
            uint32_t off = (uint32_t)(n * 128 + kk * 2);
            off ^= ((off >> 3) & 0x70);
            float w = __bfloat162float(*(const __nv_bfloat16*)(Bh + (size_t)kt * 32768 + off))
                    + __bfloat162float(*(const __nv_bfloat16*)(Bl + (size_t)kt * 32768 + off));
            float a = A[(size_t)gr * K + k] * rs;
            if (colsc) a = fmaxf(a * colsc[k] + colsh[k], 0.f);
            acc += a * w;
        }
        C[(size_t)gr * 256 + n] = acc;
        s_acc += acc * a_s[n];
        d_acc += acc * a_d[n];
    }
    as_out[gr] = s_acc; ad_out[gr] = d_acc;
#endif
}

// ---------------- zero/init (single launch) ----------------
__global__ void k_zero_all(float* bnsum, float* bnsq, float* pool, int* cnt, int* dcnt) {
    int i = blockIdx.x * blockDim.x + threadIdx.x;
    if (i < N_NODES) dcnt[i] = 0;
    if (i < N_GRAPHS * D_HID) pool[i] = 0.0f;
    if (i < D_HID) { bnsum[i] = 0.0f; bnsq[i] = 0.0f; }
    if (i < N_GRAPHS) cnt[i] = 0;
}

// ---------------- CSR build: histogram, scan, fill ----------------
__global__ void k_hist(const int* __restrict__ ei, int* __restrict__ dcnt) {
    int i = blockIdx.x * blockDim.x + threadIdx.x;
    if (i >= E_TOT) return;
    int d = (i < N_EDGES) ? ei[N_EDGES + i] : (i - N_EDGES);
    atomicAdd(&dcnt[d], 1);
}
__global__ __launch_bounds__(1024) void k_scan(const int* __restrict__ dcnt,
                                               int* __restrict__ rowoff,
                                               int* __restrict__ wr) {
    __shared__ int wsum[32];
    int t = threadIdx.x;
    int lane = t & 31, w = t >> 5;
    const int CH = (N_NODES + 1023) / 1024;   // 49
    int lo = t * CH, hi = min(lo + CH, N_NODES);
    int s = 0;
    for (int i = lo; i < hi; i++) s += dcnt[i];
    int inc = s;
    #pragma unroll
    for (int o = 1; o < 32; o <<= 1) {
        int v = __shfl_up_sync(0xffffffffu, inc, o);
        if (lane >= o) inc += v;
    }
    if (lane == 31) wsum[w] = inc;
    __syncthreads();
    if (w == 0) {
        int v = (lane < 32) ? wsum[lane] : 0;
        int wi = v;
        #pragma unroll
        for (int o = 1; o < 32; o <<= 1) {
            int u = __shfl_up_sync(0xffffffffu, wi, o);
            if (lane >= o) wi += u;
        }
        wsum[lane] = wi - v;   // exclusive
        if (lane == 31) rowoff[N_NODES] = wi;
    }
    __syncthreads();
    int run = wsum[w] + inc - s;
    for (int i = lo; i < hi; i++) {
        rowoff[i] = run; wr[i] = run;
        run += dcnt[i];
    }
}
__global__ void k_fill(const int* __restrict__ ei, int* __restrict__ wr,
                       int* __restrict__ srcid) {
    int i = blockIdx.x * blockDim.x + threadIdx.x;
    if (i >= E_TOT) return;
    int s, d;
    if (i < N_EDGES) { s = ei[i]; d = ei[N_EDGES + i]; }
    else { s = d = i - N_EDGES; }
    int pos = atomicAdd(&wr[d], 1);
    srcid[pos] = s;
}

// ---------------- relevance (cosine, float4) + graph counts ----------------
__global__ void k_rel(const float* __restrict__ claim, const float* __restrict__ x,
                      const int* __restrict__ batch, float* __restrict__ rel,
                      int* __restrict__ cnt) {
    int warp = (blockIdx.x * blockDim.x + threadIdx.x) >> 5;
    int lane = threadIdx.x & 31;
    if (warp >= N_NODES) return;
    int b = batch[warp];
    const float4* ce = (const float4*)(claim + (size_t)b * D_IN);
    const float4* xv = (const float4*)(x + (size_t)warp * D_IN);
    float dot = 0.f, nc = 0.f, nx = 0.f;
    #pragma unroll
    for (int k = lane; k < D_IN / 4; k += 32) {
        float4 c = ce[k], v = xv[k];
        dot += c.x * v.x + c.y * v.y + c.z * v.z + c.w * v.w;
        nc  += c.x * c.x + c.y * c.y + c.z * c.z + c.w * c.w;
        nx  += v.x * v.x + v.y * v.y + v.z * v.z + v.w * v.w;
    }
    dot = warp_red(dot); nc = warp_red(nc); nx = warp_red(nx);
    if (lane == 0) {
        float nrm = sqrtf(nc) * sqrtf(nx);
        rel[warp] = dot / fmaxf(nrm, EPS_COS);
        atomicAdd(&cnt[b], 1);
    }
}

// ---- score helper: attn numerator for edge (s -> d), no max-shift ----
__device__ __forceinline__ float edge_ex(const float* __restrict__ as, float add, int s) {
    float e = __ldg(as + s) + add;
    e = (e > 0.f) ? e : NEG_SLOPE * e;
    return __expf(e);
}

// ------- fused GAT edge phase (layer 1): softmax + CSR aggregation -------
__global__ void k_agg_fused(const float* __restrict__ h, float* __restrict__ agg,
                            const int* __restrict__ rowoff, const int* __restrict__ srcid,
                            const float* __restrict__ as, const float* __restrict__ ad) {
    int d = (int)(((size_t)blockIdx.x * blockDim.x + threadIdx.x) >> 5);
    int lane = threadIdx.x & 31;
    if (d >= N_NODES) return;
    int beg = rowoff[d], end = rowoff[d + 1];
    float add = ad[d];
    // pass 1: denominator (lanes over edges)
    float part = 0.f;
    for (int i = beg + lane; i < end; i += 32)
        part += edge_ex(as, add, srcid[i]);
    float invden = __frcp_rn(warp_red(part));
    // pass 2: weighted gather (warp over columns, serial edges)
    float4 a0 = make_float4(0.f, 0.f, 0.f, 0.f);
    float4 a1 = make_float4(0.f, 0.f, 0.f, 0.f);
    for (int i = beg; i < end; i++) {
        int s = srcid[i];
        float attn = edge_ex(as, add, s) * invden;
        const float4* hs = (const float4*)(h + (size_t)s * D_HID);
        float4 v0 = hs[lane], v1 = hs[lane + 32];
        a0.x += attn * v0.x; a0.y += attn * v0.y; a0.z += attn * v0.z; a0.w += attn * v0.w;
        a1.x += attn * v1.x; a1.y += attn * v1.y; a1.z += attn * v1.z; a1.w += attn * v1.w;
    }
    float4* od = (float4*)(agg + (size_t)d * D_HID);
    od[lane] = a0;
    od[lane + 32] = a1;
}

// ------- fused edge phase (layer 2): softmax + agg + relu(+b2) + mean-pool -------
__global__ void k_agg_pool_fused(const float* __restrict__ h,
                                 const int* __restrict__ rowoff, const int* __restrict__ srcid,
                                 const float* __restrict__ as, const float* __restrict__ ad,
                                 const float* __restrict__ b2,
                                 const int* __restrict__ batch,
                                 float* __restrict__ pool) {
    int d = (int)(((size_t)blockIdx.x * blockDim.x + threadIdx.x) >> 5);
    int lane = threadIdx.x & 31;
    if (d >= N_NODES) return;
    int beg = rowoff[d], end = rowoff[d + 1];
    float add = ad[d];
    float part = 0.f;
    for (int i = beg + lane; i < end; i += 32)
        part += edge_ex(as, add, srcid[i]);
    float invden = __frcp_rn(warp_red(part));
    float4 a0 = make_float4(0.f, 0.f, 0.f, 0.f);
    float4 a1 = make_float4(0.f, 0.f, 0.f, 0.f);
    for (int i = beg; i < end; i++) {
        int s = srcid[i];
        float attn = edge_ex(as, add, s) * invden;
        const float4* hs = (const float4*)(h + (size_t)s * D_HID);
        float4 v0 = hs[lane], v1 = hs[lane + 32];
        a0.x += attn * v0.x; a0.y += attn * v0.y; a0.z += attn * v0.z; a0.w += attn * v0.w;
        a1.x += attn * v1.x; a1.y += attn * v1.y; a1.z += attn * v1.z; a1.w += attn * v1.w;
    }
    float4 b0 = ((const float4*)b2)[lane];
    float4 b1 = ((const float4*)b2)[lane + 32];
    a0.x = fmaxf(a0.x + b0.x, 0.f); a0.y = fmaxf(a0.y + b0.y, 0.f);
    a0.z = fmaxf(a0.z + b0.z, 0.f); a0.w = fmaxf(a0.w + b0.w, 0.f);
    a1.x = fmaxf(a1.x + b1.x, 0.f); a1.y = fmaxf(a1.y + b1.y, 0.f);
    a1.z = fmaxf(a1.z + b1.z, 0.f); a1.w = fmaxf(a1.w + b1.w, 0.f);
    int g = batch[d];
    float4* pg = (float4*)(pool + (size_t)g * D_HID);
    asm volatile("red.global.add.v4.f32 [%0], {%1,%2,%3,%4};"
                 :: "l"(pg + lane), "f"(a0.x), "f"(a0.y), "f"(a0.z), "f"(a0.w) : "memory");
    asm volatile("red.global.add.v4.f32 [%0], {%1,%2,%3,%4};"
                 :: "l"(pg + lane + 32), "f"(a1.x), "f"(a1.y), "f"(a1.z), "f"(a1.w) : "memory");
}

// ---------------- BatchNorm stats ----------------
#define ROWS_PER_BLK 64
__global__ void k_bnstats(const float* __restrict__ h, float* __restrict__ bsum,
                          float* __restrict__ bsq) {
    int col = threadIdx.x;
    int r0 = blockIdx.x * ROWS_PER_BLK;
    int r1 = min(r0 + ROWS_PER_BLK, N_NODES);
    float s = 0.f, q = 0.f;
    for (int r = r0; r < r1; r++) {
        float v = h[(size_t)r * D_HID + col];
        s += v; q += v * v;
    }
    atomicAdd(&bsum[col], s);
    atomicAdd(&bsq[col], q);
}

// ---------------- BN finalize: per-column scale/shift ----------------
__global__ void k_bnfin(const float* __restrict__ bsum, const float* __restrict__ bsq,
                        const float* __restrict__ gamma, const float* __restrict__ beta,
                        float* __restrict__ sc, float* __restrict__ sh) {
    int col = threadIdx.x;
    float mu = bsum[col] * (1.0f / N_NODES);
    float var = bsq[col] * (1.0f / N_NODES) - mu * mu;
    float s = gamma[col] * rsqrtf(var + EPS_BN);
    sc[col] = s;
    sh[col] = beta[col] - mu * s;
}

// ---------------- classifier ----------------
__global__ void k_clf(const float* __restrict__ pool, const int* __restrict__ cnt,
                      const float* __restrict__ claim, const float* __restrict__ W,
                      const float* __restrict__ bias, float* __restrict__ out) {
    __shared__ float red[256];
    int b = blockIdx.x;
    int t = threadIdx.x;
    float c = fmaxf((float)cnt[b], 1.0f);
    float part = (pool[b * D_HID + t] / c) * W[t];
    #pragma unroll
    for (int j = 0; j < 3; j++) {
        int k = t + j * 256;
        part += claim[(size_t)b * D_IN + k] * W[D_HID + k];
    }
    red[t] = part;
    __syncthreads();
    #pragma unroll
    for (int o = 128; o; o >>= 1) {
        if (t < o) red[t] += red[t + o];
        __syncthreads();
    }
    if (t == 0) out[b] = red[0] + bias[0];
}

// ---------------- host launcher ----------------
extern "C" void kernel_launch(void* const* d_in, const int* in_sizes, int n_in,
                              void* d_out, int out_size) {
    const float* claim   = (const float*)d_in[0];
    const float* x       = (const float*)d_in[1];
    const int*   ei      = (const int*)d_in[2];
    const int*   batch   = (const int*)d_in[3];
    const float* W1      = (const float*)d_in[4];
    const float* a_src1  = (const float*)d_in[5];
    const float* a_dst1  = (const float*)d_in[6];
    // d_in[7] = b1 : provably no-op through training-mode BatchNorm
    const float* W2      = (const float*)d_in[8];
    const float* a_src2  = (const float*)d_in[9];
    const float* a_dst2  = (const float*)d_in[10];
    const float* b2      = (const float*)d_in[11];
    const float* gamma   = (const float*)d_in[12];
    const float* beta    = (const float*)d_in[13];
    const float* clfW    = (const float*)d_in[14];
    const float* clfb    = (const float*)d_in[15];
    float* out = (float*)d_out;

    float *p_rel, *p_A, *p_B, *p_as, *p_ad, *p_bnsum, *p_bnsq, *p_bnsc, *p_bnsh, *p_pool;
    int *p_cnt, *p_dcnt, *p_rowoff, *p_wr, *p_srcid;
    unsigned char *p_w1h, *p_w1l, *p_w2h, *p_w2l;
    cudaGetSymbolAddress((void**)&p_rel, g_rel);
    cudaGetSymbolAddress((void**)&p_A, g_bufA);
    cudaGetSymbolAddress((void**)&p_B, g_bufB);
    cudaGetSymbolAddress((void**)&p_as, g_as);
    cudaGetSymbolAddress((void**)&p_ad, g_ad);
    cudaGetSymbolAddress((void**)&p_bnsum, g_bnsum);
    cudaGetSymbolAddress((void**)&p_bnsq, g_bnsq);
    cudaGetSymbolAddress((void**)&p_bnsc, g_bnsc);
    cudaGetSymbolAddress((void**)&p_bnsh, g_bnsh);
    cudaGetSymbolAddress((void**)&p_pool, g_pool);
    cudaGetSymbolAddress((void**)&p_cnt, g_cnt);
    cudaGetSymbolAddress((void**)&p_dcnt, g_dcnt);
    cudaGetSymbolAddress((void**)&p_rowoff, g_rowoff);
    cudaGetSymbolAddress((void**)&p_wr, g_wr);
    cudaGetSymbolAddress((void**)&p_srcid, g_srcid);
    cudaGetSymbolAddress((void**)&p_w1h, g_w1h);
    cudaGetSymbolAddress((void**)&p_w1l, g_w1l);
    cudaGetSymbolAddress((void**)&p_w2h, g_w2h);
    cudaGetSymbolAddress((void**)&p_w2l, g_w2l);

    cudaFuncSetAttribute(k_gemm_tc, cudaFuncAttributeMaxDynamicSharedMemorySize, SM_SZ);

    const int nodeBlocks = (N_NODES + 255) / 256;
    const int edgeBlocks = (E_TOT + 255) / 256;
    const int warpNodeBlocks = (N_NODES * 32 + 255) / 256;
    const int chunkBlocks = (N_NODES + ROWS_PER_BLK - 1) / ROWS_PER_BLK;
    const int gemmBlocks = (N_NODES + 127) / 128;

    // launch order: GEMM1 stays the 4th launch (ncu captures #4).
    k_zero_all<<<nodeBlocks, 256>>>(p_bnsum, p_bnsq, p_pool, p_cnt, p_dcnt);
    k_rel<<<warpNodeBlocks, 256>>>(claim, x, batch, p_rel, p_cnt);
    k_prep_w<<<(D_IN * 256 + 255) / 256, 256>>>(W1, D_IN, p_w1h, p_w1l);
    k_gemm_tc<<<gemmBlocks, 256, SM_SZ>>>(x, D_IN, p_w1h, p_w1l, p_A,
                                          p_rel, nullptr, nullptr,
                                          a_src1, a_dst1, p_as, p_ad, N_NODES);
    k_prep_w<<<(D_HID * 256 + 255) / 256, 256>>>(W2, D_HID, p_w2h, p_w2l);
    k_hist<<<edgeBlocks, 256>>>(ei, p_dcnt);
    k_scan<<<1, 1024>>>(p_dcnt, p_rowoff, p_wr);
    k_fill<<<edgeBlocks, 256>>>(ei, p_wr, p_srcid);

    // ---- layer 1: fused softmax + aggregation ----
    k_agg_fused<<<warpNodeBlocks, 256>>>(p_A, p_B, p_rowoff, p_srcid, p_as, p_ad);

    // ---- BN stats + finalize (apply fused into GEMM2's A-loader) ----
    k_bnstats<<<chunkBlocks, 256>>>(p_B, p_bnsum, p_bnsq);
    k_bnfin<<<1, 256>>>(p_bnsum, p_bnsq, gamma, beta, p_bnsc, p_bnsh);

    // ---- layer 2: GEMM (BN+ReLU fused) + fused edge phase + pooling ----
    k_gemm_tc<<<gemmBlocks, 256, SM_SZ>>>(p_B, D_HID, p_w2h, p_w2l, p_A,
                                          nullptr, p_bnsc, p_bnsh,
                                          a_src2, a_dst2, p_as, p_ad, N_NODES);
    k_agg_pool_fused<<<warpNodeBlocks, 256>>>(p_A, p_rowoff, p_srcid, p_as, p_ad,
                                              b2, batch, p_pool);

    // ---- classifier ----
    k_clf<<<N_GRAPHS, 256>>>(p_pool, p_cnt, claim, clfW, clfb, out);
}

// round 11
// speedup vs baseline: 1.2150x; 1.0160x over previous
#include <cuda_runtime.h>
#include <cuda_bf16.h>
#include <cstdint>

#define N_NODES   50000
#define N_EDGES   400000
#define E_TOT     (N_EDGES + N_NODES)
#define N_GRAPHS  128
#define D_IN      768
#define D_HID     256
#define NEG_SLOPE 0.2f
#define EPS_COS   1e-8f
#define EPS_BN    1e-5f

#if defined(__CUDA_ARCH_FEAT_SM103_ALL) || defined(__CUDA_ARCH_SPECIFIC__)
#define HAS_TCGEN05 1
#else
#define HAS_TCGEN05 0
#endif

// ---------------- scratch (device globals; no allocation) ----------------
__device__ float    g_rel[N_NODES];
__device__ float    g_bufA[(size_t)N_NODES * D_HID];
__device__ float    g_bufB[(size_t)N_NODES * D_HID];
__device__ float    g_as[N_NODES];
__device__ float    g_ad[N_NODES];
__device__ float    g_bnsum[D_HID];
__device__ float    g_bnsq[D_HID];
__device__ float    g_bnsc[D_HID];
__device__ float    g_bnsh[D_HID];
__device__ float    g_pool[N_GRAPHS * D_HID];
__device__ int      g_cnt[N_GRAPHS];
// CSR (built once, reused by both layers)
__device__ int      g_dcnt[N_NODES];
__device__ int      g_rowoff[N_NODES + 1];
__device__ int      g_wr[N_NODES];
__device__ int      g_srcid[E_TOT];
// pre-swizzled bf16 hi/lo weight images: [ktile64][256 n-rows][128 bytes] SW128
__device__ unsigned char g_w1h[12 * 32768];
__device__ unsigned char g_w1l[12 * 32768];
__device__ unsigned char g_w2h[4 * 32768];
__device__ unsigned char g_w2l[4 * 32768];

// ---------------- PTX helpers ----------------
__device__ __forceinline__ uint32_t elect_one_pred() {
    uint32_t pred;
    asm volatile(
        "{\n\t.reg .pred p;\n\t"
        "elect.sync _|p, 0xFFFFFFFF;\n\t"
        "selp.b32 %0, 1, 0, p;\n\t}"
        : "=r"(pred));
    return pred;
}
__device__ __forceinline__ uint32_t smem_to_u32(const void* p) {
    uint32_t a;
    asm("{ .reg .u64 t; cvta.to.shared.u64 t, %1; cvt.u32.u64 %0, t; }"
        : "=r"(a) : "l"(p));
    return a;
}
#define MBARRIER_INIT(addr, cnt) \
    asm volatile("mbarrier.init.shared.b64 [%0], %1;" :: "r"((uint32_t)(addr)), "r"((uint32_t)(cnt)) : "memory")
#define MBARRIER_EXPECT_TX(addr, bytes) \
    asm volatile("mbarrier.arrive.expect_tx.shared.b64 _, [%0], %1;" \
        :: "r"((uint32_t)(addr)), "r"((uint32_t)(bytes)) : "memory")
#define MBARRIER_WAIT_PARITY(addr, parity) do { \
    uint32_t _m = (uint32_t)(addr); uint32_t _p = (uint32_t)(parity); uint32_t _d; \
    asm volatile("{\n\t.reg .pred p;\n\t" \
        "mbarrier.try_wait.parity.acquire.cta.shared::cta.b64 p, [%1], %2;\n\t" \
        "selp.b32 %0, 1, 0, p;\n\t}" : "=r"(_d) : "r"(_m), "r"(_p) : "memory"); \
    if (!_d) { \
        asm volatile("{\n\t.reg .pred P1;\n\t" \
            "WL_%=:\n\t" \
            "mbarrier.try_wait.parity.acquire.cta.shared::cta.b64 P1, [%0], %1, 0x989680;\n\t" \
            "@P1 bra.uni WD_%=;\n\t" \
            "bra.uni WL_%=;\n\t" \
            "WD_%=:\n\t}" :: "r"(_m), "r"(_p) : "memory"); \
    } \
} while (0)
#define TCGEN05_ALLOC(sa, n) \
    asm volatile("tcgen05.alloc.cta_group::1.sync.aligned.shared::cta.b32 [%0], %1;" \
        :: "r"((uint32_t)(sa)), "r"((uint32_t)(n)) : "memory")
#define TCGEN05_DEALLOC(t, n) \
    asm volatile("tcgen05.dealloc.cta_group::1.sync.aligned.b32 %0, %1;" :: "r"(t), "r"((uint32_t)(n)))
#define TCGEN05_RELINQ() \
    asm volatile("tcgen05.relinquish_alloc_permit.cta_group::1.sync.aligned;")
#define TCGEN05_COMMIT(mb) \
    asm volatile("tcgen05.commit.cta_group::1.mbarrier::arrive::one.shared::cluster.b64 [%0];" \
        :: "r"((uint32_t)(mb)) : "memory")
#define TCGEN05_FENCE_AFTER()  asm volatile("tcgen05.fence::after_thread_sync;" ::: "memory")
#define TCGEN05_FENCE_BEFORE() asm volatile("tcgen05.fence::before_thread_sync;" ::: "memory")
#define TCGEN05_WAIT_LD()      asm volatile("tcgen05.wait::ld.sync.aligned;" ::: "memory")
#define FENCE_ASYNC_SHARED()   asm volatile("fence.proxy.async.shared::cta;" ::: "memory")
#define TCGEN05_LD_X32(r, ta) \
    asm volatile("tcgen05.ld.sync.aligned.32x32b.x32.b32 " \
        "{%0, %1, %2, %3, %4, %5, %6, %7, %8, %9, %10, %11, %12, %13, %14, %15, " \
        " %16, %17, %18, %19, %20, %21, %22, %23, %24, %25, %26, %27, %28, %29, %30, %31}, [%32];" \
        : "=r"((r)[0]), "=r"((r)[1]), "=r"((r)[2]), "=r"((r)[3]), \
          "=r"((r)[4]), "=r"((r)[5]), "=r"((r)[6]), "=r"((r)[7]), \
          "=r"((r)[8]), "=r"((r)[9]), "=r"((r)[10]), "=r"((r)[11]), \
          "=r"((r)[12]), "=r"((r)[13]), "=r"((r)[14]), "=r"((r)[15]), \
          "=r"((r)[16]), "=r"((r)[17]), "=r"((r)[18]), "=r"((r)[19]), \
          "=r"((r)[20]), "=r"((r)[21]), "=r"((r)[22]), "=r"((r)[23]), \
          "=r"((r)[24]), "=r"((r)[25]), "=r"((r)[26]), "=r"((r)[27]), \
          "=r"((r)[28]), "=r"((r)[29]), "=r"((r)[30]), "=r"((r)[31]) \
        : "r"(ta))

static constexpr uint64_t SMEM_DESC_BASE_SW128 =
    (uint64_t(2) << 61) | (uint64_t(1) << 46) | (uint64_t(64) << 32) | (uint64_t(1) << 16);
__device__ __forceinline__ uint64_t make_desc(uint32_t addr) {
    return SMEM_DESC_BASE_SW128 | ((uint64_t)(addr >> 4) & 0x3FFF);
}
// idesc: dtype=F32, atype=btype=BF16, N=256, M=128
#define IDESC_G 0x8400490u

#if HAS_TCGEN05
__device__ __forceinline__ void mma_f16_ss(uint32_t d, uint64_t ad, uint64_t bd,
                                           uint32_t idesc, uint32_t en) {
    asm volatile(
        "{\n\t.reg .pred p;\n\t"
        "setp.ne.u32 p, %5, 0;\n\t"
        "tcgen05.mma.cta_group::1.kind::f16 [%0], %1, %2, %3, {%4, %4, %4, %4}, p;\n\t}"
        :: "r"(d), "l"(ad), "l"(bd), "r"(idesc), "r"(0u), "r"(en) : "memory");
}
__device__ __forceinline__ void bulk_cp(uint32_t dst, const void* src, uint32_t bytes,
                                        uint32_t mb) {
    asm volatile(
        "cp.async.bulk.shared::cta.global.mbarrier::complete_tx::bytes [%0], [%1], %2, [%3];"
        :: "r"(dst), "l"(src), "r"(bytes), "r"(mb) : "memory");
}
#endif

__device__ __forceinline__ float warp_red(float v) {
    #pragma unroll
    for (int o = 16; o; o >>= 1) v += __shfl_xor_sync(0xffffffffu, v, o);
    return v;
}
__device__ __forceinline__ uint32_t pack_bf(__nv_bfloat16 a, __nv_bfloat16 b) {
    return (uint32_t)__bfloat16_as_ushort(a) | ((uint32_t)__bfloat16_as_ushort(b) << 16);
}
// packed pair convert: res = bf16(a) | bf16(b)<<16
#define CVT2(res, a_, b_) \
    asm("cvt.rn.bf16x2.f32 %0, %1, %2;" : "=r"(res) : "f"(b_), "f"(a_))

// convert float4 -> packed {hi01, hi23, lo01, lo23}
__device__ __forceinline__ uint4 split_pack(float4 v) {
    uint4 pk;
    CVT2(pk.x, v.x, v.y);
    CVT2(pk.y, v.z, v.w);
    float h0 = __uint_as_float(pk.x << 16);
    float h1 = __uint_as_float(pk.x & 0xFFFF0000u);
    float h2 = __uint_as_float(pk.y << 16);
    float h3 = __uint_as_float(pk.y & 0xFFFF0000u);
    CVT2(pk.z, v.x - h0, v.y - h1);
    CVT2(pk.w, v.z - h2, v.w - h3);
    return pk;
}

// ---------------- weight prep: fp32 [K,256] -> SW128 bf16 hi/lo, K=64 tiles ----------------
__global__ void k_prep_w(const float* __restrict__ W, int K,
                         unsigned char* __restrict__ hi, unsigned char* __restrict__ lo) {
    int idx = blockIdx.x * blockDim.x + threadIdx.x;
    if (idx >= K * 256) return;
    int k = idx >> 8, n = idx & 255;
    float v = W[idx];
    __nv_bfloat16 h = __float2bfloat16_rn(v);
    __nv_bfloat16 l = __float2bfloat16_rn(v - __bfloat162float(h));
    int kt = k >> 6, kk = k & 63;
    uint32_t off = (uint32_t)(n * 128 + kk * 2);
    off ^= ((off >> 3) & 0x70);
    size_t base = (size_t)kt * 32768 + off;
    *(__nv_bfloat16*)(hi + base) = h;
    *(__nv_bfloat16*)(lo + base) = l;
}

// -------- tcgen05 GEMM: convert-in-MMA-shadow, K=64, 256 thr, occ=2 ----
#define SM_TPTR 0
#define SM_MBAR 8
#define SM_MBT  16
#define SM_ASV  1024
#define SM_ADV  2048
#define SM_AH   3072
#define SM_AL   (SM_AH + 16384)
#define SM_BH   (SM_AL + 16384)
#define SM_BL   (SM_BH + 32768)
#define SM_SZ   (SM_BL + 32768)

__global__ __launch_bounds__(256, 2) void k_gemm_tc(
    const float* __restrict__ A, int K,
    const unsigned char* __restrict__ Bh, const unsigned char* __restrict__ Bl,
    float* __restrict__ C,
    const float* __restrict__ rowscale,
    const float* __restrict__ colsc, const float* __restrict__ colsh,
    const float* __restrict__ a_s, const float* __restrict__ a_d,
    float* __restrict__ as_out, float* __restrict__ ad_out, int M)
{
#if HAS_TCGEN05
    extern __shared__ char smem[];
    uint32_t sb = smem_to_u32(smem);
    int tid = threadIdx.x, wid = tid >> 5, lane = tid & 31;
    int m0 = blockIdx.x * 128;

    if (tid == 0) { MBARRIER_INIT(sb + SM_MBAR, 1); MBARRIER_INIT(sb + SM_MBT, 1); }
    if (wid == 0) TCGEN05_ALLOC(sb + SM_TPTR, 256);
    float* sAS = (float*)(smem + SM_ASV);
    float* sAD = (float*)(smem + SM_ADV);
    if (tid < 256) { sAS[tid] = a_s[tid]; sAD[tid] = a_d[tid]; }
    __syncthreads();
    uint32_t tmem;
    asm volatile("ld.shared.b32 %0, [%1];" : "=r"(tmem) : "r"(sb + SM_TPTR));
    if (wid == 0) TCGEN05_RELINQ();

    const uint64_t aH = make_desc(sb + SM_AH);
    const uint64_t aL = make_desc(sb + SM_AL);
    const uint64_t bH = make_desc(sb + SM_BH);
    const uint64_t bL = make_desc(sb + SM_BL);

    int rbase = tid >> 4;        // 0..15
    int cq = (tid & 15) << 2;    // 0,4,...,60
    int ph = 0, ph_t = 0;
    const int nk = K >> 6;

    float s_row[8];
    #pragma unroll
    for (int i = 0; i < 8; i++) {
        int gr = m0 + i * 16 + rbase;
        s_row[i] = (rowscale && gr < M) ? rowscale[gr] : 1.0f;
    }
    // SMEM swizzled offsets per row chunk (constant over tiles)
    uint32_t so[8];
    #pragma unroll
    for (int i = 0; i < 8; i++) {
        uint32_t off = (uint32_t)((i * 16 + rbase) * 128 + cq * 2);
        so[i] = off ^ ((off >> 3) & 0x70);
    }

    // ---- convert tile kt into pk[] (pure compute; runs in MMA shadow) ----
    auto convert_tile = [&](int kt, uint4* pk) {
        int k0 = kt << 6;
        float4 csc = make_float4(1.f, 1.f, 1.f, 1.f);
        float4 csh = make_float4(0.f, 0.f, 0.f, 0.f);
        if (colsc) {
            csc = *(const float4*)(colsc + k0 + cq);
            csh = *(const float4*)(colsh + k0 + cq);
        }
        float4 va[8];
        #pragma unroll
        for (int i = 0; i < 8; i++) {
            int gr = m0 + i * 16 + rbase;
            va[i] = (gr < M) ? *(const float4*)(A + (size_t)gr * K + k0 + cq)
                             : make_float4(0.f, 0.f, 0.f, 0.f);
        }
        #pragma unroll
        for (int i = 0; i < 8; i++) {
            float4 v = va[i];
            float sc = s_row[i];
            v.x *= sc; v.y *= sc; v.z *= sc; v.w *= sc;
            if (colsc) {
                v.x = fmaxf(v.x * csc.x + csh.x, 0.f);
                v.y = fmaxf(v.y * csc.y + csh.y, 0.f);
                v.z = fmaxf(v.z * csc.z + csh.z, 0.f);
                v.w = fmaxf(v.w * csc.w + csh.w, 0.f);
            }
            pk[i] = split_pack(v);
        }
    };

    uint4 pk[8];
    convert_tile(0, pk);

    for (int kt = 0; kt < nk; kt++) {
        // stage still read by MMA(kt-1): wait its commit (mostly drained by
        // the convert that ran in its shadow)
        if (kt) { MBARRIER_WAIT_PARITY(sb + SM_MBAR, ph); ph ^= 1; }

        if (tid == 0) {
            MBARRIER_EXPECT_TX(sb + SM_MBT, 65536u);
            bulk_cp(sb + SM_BH, Bh + (size_t)kt * 32768, 32768u, sb + SM_MBT);
            bulk_cp(sb + SM_BL, Bl + (size_t)kt * 32768, 32768u, sb + SM_MBT);
        }
        // ---- pure STS of pre-converted tile ----
        #pragma unroll
        for (int i = 0; i < 8; i++) {
            *(uint2*)(smem + SM_AH + so[i]) = make_uint2(pk[i].x, pk[i].y);
            *(uint2*)(smem + SM_AL + so[i]) = make_uint2(pk[i].z, pk[i].w);
        }
        FENCE_ASYNC_SHARED();
        __syncthreads();
        // ---- issue MMA(kt) ----
        if (wid == 0) {
            MBARRIER_WAIT_PARITY(sb + SM_MBT, ph_t);
            if (elect_one_pred()) {
                #pragma unroll
                for (int sp = 0; sp < 3; sp++) {
                    uint64_t ad = (sp == 2) ? aL : aH;
                    uint64_t bd = (sp == 1) ? bL : bH;
                    #pragma unroll
                    for (int c = 0; c < 4; c++) {
                        uint32_t en = (kt == 0 && sp == 0 && c == 0) ? 0u : 1u;
                        mma_f16_ss(tmem, ad + c * 2, bd + c * 2, IDESC_G, en);
                    }
                }
                TCGEN05_COMMIT(sb + SM_MBAR);
            }
        }
        ph_t ^= 1;
        // ---- convert tile kt+1 while MMA(kt) drains ----
        if (kt + 1 < nk) convert_tile(kt + 1, pk);
    }
    MBARRIER_WAIT_PARITY(sb + SM_MBAR, ph);
    TCGEN05_FENCE_AFTER();

    if (wid < 4) {
        int row = m0 + wid * 32 + lane;
        float s_acc = 0.f, d_acc = 0.f;
        #pragma unroll
        for (int j = 0; j < 8; j++) {
            uint32_t r[32];
            TCGEN05_LD_X32(r, tmem + j * 32);
            TCGEN05_WAIT_LD();
            #pragma unroll
            for (int q = 0; q < 32; q++) {
                float f = __uint_as_float(r[q]);
                s_acc += f * sAS[j * 32 + q];
                d_acc += f * sAD[j * 32 + q];
            }
            if (row < M) {
                float4* dst = (float4*)(C + (size_t)row * D_HID + j * 32);
                #pragma unroll
                for (int q = 0; q < 8; q++)
                    dst[q] = make_float4(__uint_as_float(r[q * 4 + 0]), __uint_as_float(r[q * 4 + 1]),
                                         __uint_as_float(r[q * 4 + 2]), __uint_as_float(r[q * 4 + 3]));
            }
        }
        if (row < M) { as_out[row] = s_acc; ad_out[row] = d_acc; }
        TCGEN05_FENCE_BEFORE();
    }
    __syncthreads();
    if (tid == 0) {
        asm volatile("mbarrier.inval.shared.b64 [%0];" :: "r"(sb + SM_MBAR) : "memory");
        asm volatile("mbarrier.inval.shared.b64 [%0];" :: "r"(sb + SM_MBT) : "memory");
    }
    __syncthreads();
    if (wid == 0) TCGEN05_DEALLOC(tmem, 256);
#else
    // Correct scalar fallback for the non-arch-specific PTX pass.
    int tid = threadIdx.x;
    if (tid >= 128) return;
    int gr = blockIdx.x * 128 + tid;
    if (gr >= M) return;
    float rs = rowscale ? rowscale[gr] : 1.0f;
    float s_acc = 0.f, d_acc = 0.f;
    for (int n = 0; n < 256; n++) {
        float acc = 0.f;
        for (int k = 0; k < K; k++) {
            int kt = k >> 6, kk = k & 63;
            uint32_t off = (uint32_t)(n * 128 + kk * 2);
            off ^= ((off >> 3) & 0x70);
            float w = __bfloat162float(*(const __nv_bfloat16*)(Bh + (size_t)kt * 32768 + off))
                    + __bfloat162float(*(const __nv_bfloat16*)(Bl + (size_t)kt * 32768 + off));
            float a = A[(size_t)gr * K + k] * rs;
            if (colsc) a = fmaxf(a * colsc[k] + colsh[k], 0.f);
            acc += a * w;
        }
        C[(size_t)gr * 256 + n] = acc;
        s_acc += acc * a_s[n];
        d_acc += acc * a_d[n];
    }
    as_out[gr] = s_acc; ad_out[gr] = d_acc;
#endif
}

// ---------------- zero/init (single launch) ----------------
__global__ void k_zero_all(float* bnsum, float* bnsq, float* pool, int* cnt, int* dcnt) {
    int i = blockIdx.x * blockDim.x + threadIdx.x;
    if (i < N_NODES) dcnt[i] = 0;
    if (i < N_GRAPHS * D_HID) pool[i] = 0.0f;
    if (i < D_HID) { bnsum[i] = 0.0f; bnsq[i] = 0.0f; }
    if (i < N_GRAPHS) cnt[i] = 0;
}

// ---------------- CSR build: histogram, scan, fill ----------------
__global__ void k_hist(const int* __restrict__ ei, int* __restrict__ dcnt) {
    int i = blockIdx.x * blockDim.x + threadIdx.x;
    if (i >= E_TOT) return;
    int d = (i < N_EDGES) ? ei[N_EDGES + i] : (i - N_EDGES);
    atomicAdd(&dcnt[d], 1);
}
__global__ __launch_bounds__(1024) void k_scan(const int* __restrict__ dcnt,
                                               int* __restrict__ rowoff,
                                               int* __restrict__ wr) {
    __shared__ int wsum[32];
    int t = threadIdx.x;
    int lane = t & 31, w = t >> 5;
    const int CH = (N_NODES + 1023) / 1024;   // 49
    int lo = t * CH, hi = min(lo + CH, N_NODES);
    int s = 0;
    for (int i = lo; i < hi; i++) s += dcnt[i];
    int inc = s;
    #pragma unroll
    for (int o = 1; o < 32; o <<= 1) {
        int v = __shfl_up_sync(0xffffffffu, inc, o);
        if (lane >= o) inc += v;
    }
    if (lane == 31) wsum[w] = inc;
    __syncthreads();
    if (w == 0) {
        int v = (lane < 32) ? wsum[lane] : 0;
        int wi = v;
        #pragma unroll
        for (int o = 1; o < 32; o <<= 1) {
            int u = __shfl_up_sync(0xffffffffu, wi, o);
            if (lane >= o) wi += u;
        }
        wsum[lane] = wi - v;   // exclusive
        if (lane == 31) rowoff[N_NODES] = wi;
    }
    __syncthreads();
    int run = wsum[w] + inc - s;
    for (int i = lo; i < hi; i++) {
        rowoff[i] = run; wr[i] = run;
        run += dcnt[i];
    }
}
__global__ void k_fill(const int* __restrict__ ei, int* __restrict__ wr,
                       int* __restrict__ srcid) {
    int i = blockIdx.x * blockDim.x + threadIdx.x;
    if (i >= E_TOT) return;
    int s, d;
    if (i < N_EDGES) { s = ei[i]; d = ei[N_EDGES + i]; }
    else { s = d = i - N_EDGES; }
    int pos = atomicAdd(&wr[d], 1);
    srcid[pos] = s;
}

// ---------------- relevance (cosine, float4) + graph counts ----------------
__global__ void k_rel(const float* __restrict__ claim, const float* __restrict__ x,
                      const int* __restrict__ batch, float* __restrict__ rel,
                      int* __restrict__ cnt) {
    int warp = (blockIdx.x * blockDim.x + threadIdx.x) >> 5;
    int lane = threadIdx.x & 31;
    if (warp >= N_NODES) return;
    int b = batch[warp];
    const float4* ce = (const float4*)(claim + (size_t)b * D_IN);
    const float4* xv = (const float4*)(x + (size_t)warp * D_IN);
    float dot = 0.f, nc = 0.f, nx = 0.f;
    #pragma unroll
    for (int k = lane; k < D_IN / 4; k += 32) {
        float4 c = ce[k], v = xv[k];
        dot += c.x * v.x + c.y * v.y + c.z * v.z + c.w * v.w;
        nc  += c.x * c.x + c.y * c.y + c.z * c.z + c.w * c.w;
        nx  += v.x * v.x + v.y * v.y + v.z * v.z + v.w * v.w;
    }
    dot = warp_red(dot); nc = warp_red(nc); nx = warp_red(nx);
    if (lane == 0) {
        float nrm = sqrtf(nc) * sqrtf(nx);
        rel[warp] = dot / fmaxf(nrm, EPS_COS);
        atomicAdd(&cnt[b], 1);
    }
}

// ---- score helper: attn numerator for edge (s -> d), no max-shift ----
__device__ __forceinline__ float edge_ex(const float* __restrict__ as, float add, int s) {
    float e = __ldg(as + s) + add;
    e = (e > 0.f) ? e : NEG_SLOPE * e;
    return __expf(e);
}

// ------- fused GAT edge phase (layer 1): softmax + CSR aggregation -------
__global__ void k_agg_fused(const float* __restrict__ h, float* __restrict__ agg,
                            const int* __restrict__ rowoff, const int* __restrict__ srcid,
                            const float* __restrict__ as, const float* __restrict__ ad) {
    int d = (int)(((size_t)blockIdx.x * blockDim.x + threadIdx.x) >> 5);
    int lane = threadIdx.x & 31;
    if (d >= N_NODES) return;
    int beg = rowoff[d], end = rowoff[d + 1];
    float add = ad[d];
    float part = 0.f;
    for (int i = beg + lane; i < end; i += 32)
        part += edge_ex(as, add, srcid[i]);
    float invden = __frcp_rn(warp_red(part));
    float4 a0 = make_float4(0.f, 0.f, 0.f, 0.f);
    float4 a1 = make_float4(0.f, 0.f, 0.f, 0.f);
    for (int i = beg; i < end; i++) {
        int s = srcid[i];
        float attn = edge_ex(as, add, s) * invden;
        const float4* hs = (const float4*)(h + (size_t)s * D_HID);
        float4 v0 = hs[lane], v1 = hs[lane + 32];
        a0.x += attn * v0.x; a0.y += attn * v0.y; a0.z += attn * v0.z; a0.w += attn * v0.w;
        a1.x += attn * v1.x; a1.y += attn * v1.y; a1.z += attn * v1.z; a1.w += attn * v1.w;
    }
    float4* od = (float4*)(agg + (size_t)d * D_HID);
    od[lane] = a0;
    od[lane + 32] = a1;
}

// ------- fused edge phase (layer 2): softmax + agg + relu(+b2) + mean-pool -------
__global__ void k_agg_pool_fused(const float* __restrict__ h,
                                 const int* __restrict__ rowoff, const int* __restrict__ srcid,
                                 const float* __restrict__ as, const float* __restrict__ ad,
                                 const float* __restrict__ b2,
                                 const int* __restrict__ batch,
                                 float* __restrict__ pool) {
    int d = (int)(((size_t)blockIdx.x * blockDim.x + threadIdx.x) >> 5);
    int lane = threadIdx.x & 31;
    if (d >= N_NODES) return;
    int beg = rowoff[d], end = rowoff[d + 1];
    float add = ad[d];
    float part = 0.f;
    for (int i = beg + lane; i < end; i += 32)
        part += edge_ex(as, add, srcid[i]);
    float invden = __frcp_rn(warp_red(part));
    float4 a0 = make_float4(0.f, 0.f, 0.f, 0.f);
    float4 a1 = make_float4(0.f, 0.f, 0.f, 0.f);
    for (int i = beg; i < end; i++) {
        int s = srcid[i];
        float attn = edge_ex(as, add, s) * invden;
        const float4* hs = (const float4*)(h + (size_t)s * D_HID);
        float4 v0 = hs[lane], v1 = hs[lane + 32];
        a0.x += attn * v0.x; a0.y += attn * v0.y; a0.z += attn * v0.z; a0.w += attn * v0.w;
        a1.x += attn * v1.x; a1.y += attn * v1.y; a1.z += attn * v1.z; a1.w += attn * v1.w;
    }
    float4 b0 = ((const float4*)b2)[lane];
    float4 b1 = ((const float4*)b2)[lane + 32];
    a0.x = fmaxf(a0.x + b0.x, 0.f); a0.y = fmaxf(a0.y + b0.y, 0.f);
    a0.z = fmaxf(a0.z + b0.z, 0.f); a0.w = fmaxf(a0.w + b0.w, 0.f);
    a1.x = fmaxf(a1.x + b1.x, 0.f); a1.y = fmaxf(a1.y + b1.y, 0.f);
    a1.z = fmaxf(a1.z + b1.z, 0.f); a1.w = fmaxf(a1.w + b1.w, 0.f);
    int g = batch[d];
    float4* pg = (float4*)(pool + (size_t)g * D_HID);
    asm volatile("red.global.add.v4.f32 [%0], {%1,%2,%3,%4};"
                 :: "l"(pg + lane), "f"(a0.x), "f"(a0.y), "f"(a0.z), "f"(a0.w) : "memory");
    asm volatile("red.global.add.v4.f32 [%0], {%1,%2,%3,%4};"
                 :: "l"(pg + lane + 32), "f"(a1.x), "f"(a1.y), "f"(a1.z), "f"(a1.w) : "memory");
}

// ---------------- BatchNorm stats ----------------
#define ROWS_PER_BLK 64
__global__ void k_bnstats(const float* __restrict__ h, float* __restrict__ bsum,
                          float* __restrict__ bsq) {
    int col = threadIdx.x;
    int r0 = blockIdx.x * ROWS_PER_BLK;
    int r1 = min(r0 + ROWS_PER_BLK, N_NODES);
    float s = 0.f, q = 0.f;
    for (int r = r0; r < r1; r++) {
        float v = h[(size_t)r * D_HID + col];
        s += v; q += v * v;
    }
    atomicAdd(&bsum[col], s);
    atomicAdd(&bsq[col], q);
}

// ---------------- BN finalize: per-column scale/shift ----------------
__global__ void k_bnfin(const float* __restrict__ bsum, const float* __restrict__ bsq,
                        const float* __restrict__ gamma, const float* __restrict__ beta,
                        float* __restrict__ sc, float* __restrict__ sh) {
    int col = threadIdx.x;
    float mu = bsum[col] * (1.0f / N_NODES);
    float var = bsq[col] * (1.0f / N_NODES) - mu * mu;
    float s = gamma[col] * rsqrtf(var + EPS_BN);
    sc[col] = s;
    sh[col] = beta[col] - mu * s;
}

// ---------------- classifier ----------------
__global__ void k_clf(const float* __restrict__ pool, const int* __restrict__ cnt,
                      const float* __restrict__ claim, const float* __restrict__ W,
                      const float* __restrict__ bias, float* __restrict__ out) {
    __shared__ float red[256];
    int b = blockIdx.x;
    int t = threadIdx.x;
    float c = fmaxf((float)cnt[b], 1.0f);
    float part = (pool[b * D_HID + t] / c) * W[t];
    #pragma unroll
    for (int j = 0; j < 3; j++) {
        int k = t + j * 256;
        part += claim[(size_t)b * D_IN + k] * W[D_HID + k];
    }
    red[t] = part;
    __syncthreads();
    #pragma unroll
    for (int o = 128; o; o >>= 1) {
        if (t < o) red[t] += red[t + o];
        __syncthreads();
    }
    if (t == 0) out[b] = red[0] + bias[0];
}

// ---------------- host launcher ----------------
extern "C" void kernel_launch(void* const* d_in, const int* in_sizes, int n_in,
                              void* d_out, int out_size) {
    const float* claim   = (const float*)d_in[0];
    const float* x       = (const float*)d_in[1];
    const int*   ei      = (const int*)d_in[2];
    const int*   batch   = (const int*)d_in[3];
    const float* W1      = (const float*)d_in[4];
    const float* a_src1  = (const float*)d_in[5];
    const float* a_dst1  = (const float*)d_in[6];
    // d_in[7] = b1 : provably no-op through training-mode BatchNorm
    const float* W2      = (const float*)d_in[8];
    const float* a_src2  = (const float*)d_in[9];
    const float* a_dst2  = (const float*)d_in[10];
    const float* b2      = (const float*)d_in[11];
    const float* gamma   = (const float*)d_in[12];
    const float* beta    = (const float*)d_in[13];
    const float* clfW    = (const float*)d_in[14];
    const float* clfb    = (const float*)d_in[15];
    float* out = (float*)d_out;

    float *p_rel, *p_A, *p_B, *p_as, *p_ad, *p_bnsum, *p_bnsq, *p_bnsc, *p_bnsh, *p_pool;
    int *p_cnt, *p_dcnt, *p_rowoff, *p_wr, *p_srcid;
    unsigned char *p_w1h, *p_w1l, *p_w2h, *p_w2l;
    cudaGetSymbolAddress((void**)&p_rel, g_rel);
    cudaGetSymbolAddress((void**)&p_A, g_bufA);
    cudaGetSymbolAddress((void**)&p_B, g_bufB);
    cudaGetSymbolAddress((void**)&p_as, g_as);
    cudaGetSymbolAddress((void**)&p_ad, g_ad);
    cudaGetSymbolAddress((void**)&p_bnsum, g_bnsum);
    cudaGetSymbolAddress((void**)&p_bnsq, g_bnsq);
    cudaGetSymbolAddress((void**)&p_bnsc, g_bnsc);
    cudaGetSymbolAddress((void**)&p_bnsh, g_bnsh);
    cudaGetSymbolAddress((void**)&p_pool, g_pool);
    cudaGetSymbolAddress((void**)&p_cnt, g_cnt);
    cudaGetSymbolAddress((void**)&p_dcnt, g_dcnt);
    cudaGetSymbolAddress((void**)&p_rowoff, g_rowoff);
    cudaGetSymbolAddress((void**)&p_wr, g_wr);
    cudaGetSymbolAddress((void**)&p_srcid, g_srcid);
    cudaGetSymbolAddress((void**)&p_w1h, g_w1h);
    cudaGetSymbolAddress((void**)&p_w1l, g_w1l);
    cudaGetSymbolAddress((void**)&p_w2h, g_w2h);
    cudaGetSymbolAddress((void**)&p_w2l, g_w2l);

    cudaFuncSetAttribute(k_gemm_tc, cudaFuncAttributeMaxDynamicSharedMemorySize, SM_SZ);

    const int nodeBlocks = (N_NODES + 255) / 256;
    const int edgeBlocks = (E_TOT + 255) / 256;
    const int warpNodeBlocks = (N_NODES * 32 + 255) / 256;
    const int chunkBlocks = (N_NODES + ROWS_PER_BLK - 1) / ROWS_PER_BLK;
    const int gemmBlocks = (N_NODES + 127) / 128;

    // launch order: GEMM1 stays the 4th launch (ncu captures #4).
    k_zero_all<<<nodeBlocks, 256>>>(p_bnsum, p_bnsq, p_pool, p_cnt, p_dcnt);
    k_rel<<<warpNodeBlocks, 256>>>(claim, x, batch, p_rel, p_cnt);
    k_prep_w<<<(D_IN * 256 + 255) / 256, 256>>>(W1, D_IN, p_w1h, p_w1l);
    k_gemm_tc<<<gemmBlocks, 256, SM_SZ>>>(x, D_IN, p_w1h, p_w1l, p_A,
                                          p_rel, nullptr, nullptr,
                                          a_src1, a_dst1, p_as, p_ad, N_NODES);
    k_prep_w<<<(D_HID * 256 + 255) / 256, 256>>>(W2, D_HID, p_w2h, p_w2l);
    k_hist<<<edgeBlocks, 256>>>(ei, p_dcnt);
    k_scan<<<1, 1024>>>(p_dcnt, p_rowoff, p_wr);
    k_fill<<<edgeBlocks, 256>>>(ei, p_wr, p_srcid);

    // ---- layer 1: fused softmax + aggregation ----
    k_agg_fused<<<warpNodeBlocks, 256>>>(p_A, p_B, p_rowoff, p_srcid, p_as, p_ad);

    // ---- BN stats + finalize (apply fused into GEMM2's A-loader) ----
    k_bnstats<<<chunkBlocks, 256>>>(p_B, p_bnsum, p_bnsq);
    k_bnfin<<<1, 256>>>(p_bnsum, p_bnsq, gamma, beta, p_bnsc, p_bnsh);

    // ---- layer 2: GEMM (BN+ReLU fused) + fused edge phase + pooling ----
    k_gemm_tc<<<gemmBlocks, 256, SM_SZ>>>(p_B, D_HID, p_w2h, p_w2l, p_A,
                                          nullptr, p_bnsc, p_bnsh,
                                          a_src2, a_dst2, p_as, p_ad, N_NODES);
    k_agg_pool_fused<<<warpNodeBlocks, 256>>>(p_A, p_rowoff, p_srcid, p_as, p_ad,
                                              b2, batch, p_pool);

    // ---- classifier ----
    k_clf<<<N_GRAPHS, 256>>>(p_pool, p_cnt, claim, clfW, clfb, out);
}

// round 12
// speedup vs baseline: 1.2281x; 1.0108x over previous
#include <cuda_runtime.h>
#include <cuda_bf16.h>
#include <cstdint>

#define N_NODES   50000
#define N_EDGES   400000
#define E_TOT     (N_EDGES + N_NODES)
#define N_GRAPHS  128
#define D_IN      768
#define D_HID     256
#define NEG_SLOPE 0.2f
#define EPS_COS   1e-8f
#define EPS_BN    1e-5f

#if defined(__CUDA_ARCH_FEAT_SM103_ALL) || defined(__CUDA_ARCH_SPECIFIC__)
#define HAS_TCGEN05 1
#else
#define HAS_TCGEN05 0
#endif

// ---------------- scratch (device globals; no allocation) ----------------
__device__ float    g_rel[N_NODES];
__device__ float    g_bufA[(size_t)N_NODES * D_HID];
__device__ float    g_bufB[(size_t)N_NODES * D_HID];
__device__ float    g_as[N_NODES];
__device__ float    g_ad[N_NODES];
__device__ float    g_bnsum[D_HID];
__device__ float    g_bnsq[D_HID];
__device__ float    g_bnsc[D_HID];
__device__ float    g_bnsh[D_HID];
__device__ float    g_pool[N_GRAPHS * D_HID];
__device__ int      g_cnt[N_GRAPHS];
// CSR (built once, reused by both layers)
__device__ int      g_dcnt[N_NODES];
__device__ int      g_rowoff[N_NODES + 1];
__device__ int      g_wr[N_NODES];
__device__ int      g_srcid[E_TOT];
// pre-swizzled bf16 hi/lo weight images: [ktile64][256 n-rows][128 bytes] SW128
__device__ unsigned char g_w1h[12 * 32768];
__device__ unsigned char g_w1l[12 * 32768];
__device__ unsigned char g_w2h[4 * 32768];
__device__ unsigned char g_w2l[4 * 32768];

// ---------------- PTX helpers ----------------
__device__ __forceinline__ uint32_t elect_one_pred() {
    uint32_t pred;
    asm volatile(
        "{\n\t.reg .pred p;\n\t"
        "elect.sync _|p, 0xFFFFFFFF;\n\t"
        "selp.b32 %0, 1, 0, p;\n\t}"
        : "=r"(pred));
    return pred;
}
__device__ __forceinline__ uint32_t smem_to_u32(const void* p) {
    uint32_t a;
    asm("{ .reg .u64 t; cvta.to.shared.u64 t, %1; cvt.u32.u64 %0, t; }"
        : "=r"(a) : "l"(p));
    return a;
}
#define MBARRIER_INIT(addr, cnt) \
    asm volatile("mbarrier.init.shared.b64 [%0], %1;" :: "r"((uint32_t)(addr)), "r"((uint32_t)(cnt)) : "memory")
#define MBARRIER_EXPECT_TX(addr, bytes) \
    asm volatile("mbarrier.arrive.expect_tx.shared.b64 _, [%0], %1;" \
        :: "r"((uint32_t)(addr)), "r"((uint32_t)(bytes)) : "memory")
#define MBARRIER_WAIT_PARITY(addr, parity) do { \
    uint32_t _m = (uint32_t)(addr); uint32_t _p = (uint32_t)(parity); uint32_t _d; \
    asm volatile("{\n\t.reg .pred p;\n\t" \
        "mbarrier.try_wait.parity.acquire.cta.shared::cta.b64 p, [%1], %2;\n\t" \
        "selp.b32 %0, 1, 0, p;\n\t}" : "=r"(_d) : "r"(_m), "r"(_p) : "memory"); \
    if (!_d) { \
        asm volatile("{\n\t.reg .pred P1;\n\t" \
            "WL_%=:\n\t" \
            "mbarrier.try_wait.parity.acquire.cta.shared::cta.b64 P1, [%0], %1, 0x989680;\n\t" \
            "@P1 bra.uni WD_%=;\n\t" \
            "bra.uni WL_%=;\n\t" \
            "WD_%=:\n\t}" :: "r"(_m), "r"(_p) : "memory"); \
    } \
} while (0)
#define TCGEN05_ALLOC(sa, n) \
    asm volatile("tcgen05.alloc.cta_group::1.sync.aligned.shared::cta.b32 [%0], %1;" \
        :: "r"((uint32_t)(sa)), "r"((uint32_t)(n)) : "memory")
#define TCGEN05_DEALLOC(t, n) \
    asm volatile("tcgen05.dealloc.cta_group::1.sync.aligned.b32 %0, %1;" :: "r"(t), "r"((uint32_t)(n)))
#define TCGEN05_RELINQ() \
    asm volatile("tcgen05.relinquish_alloc_permit.cta_group::1.sync.aligned;")
#define TCGEN05_COMMIT(mb) \
    asm volatile("tcgen05.commit.cta_group::1.mbarrier::arrive::one.shared::cluster.b64 [%0];" \
        :: "r"((uint32_t)(mb)) : "memory")
#define TCGEN05_FENCE_AFTER()  asm volatile("tcgen05.fence::after_thread_sync;" ::: "memory")
#define TCGEN05_FENCE_BEFORE() asm volatile("tcgen05.fence::before_thread_sync;" ::: "memory")
#define TCGEN05_WAIT_LD()      asm volatile("tcgen05.wait::ld.sync.aligned;" ::: "memory")
#define FENCE_ASYNC_SHARED()   asm volatile("fence.proxy.async.shared::cta;" ::: "memory")
#define TCGEN05_LD_X32(r, ta) \
    asm volatile("tcgen05.ld.sync.aligned.32x32b.x32.b32 " \
        "{%0, %1, %2, %3, %4, %5, %6, %7, %8, %9, %10, %11, %12, %13, %14, %15, " \
        " %16, %17, %18, %19, %20, %21, %22, %23, %24, %25, %26, %27, %28, %29, %30, %31}, [%32];" \
        : "=r"((r)[0]), "=r"((r)[1]), "=r"((r)[2]), "=r"((r)[3]), \
          "=r"((r)[4]), "=r"((r)[5]), "=r"((r)[6]), "=r"((r)[7]), \
          "=r"((r)[8]), "=r"((r)[9]), "=r"((r)[10]), "=r"((r)[11]), \
          "=r"((r)[12]), "=r"((r)[13]), "=r"((r)[14]), "=r"((r)[15]), \
          "=r"((r)[16]), "=r"((r)[17]), "=r"((r)[18]), "=r"((r)[19]), \
          "=r"((r)[20]), "=r"((r)[21]), "=r"((r)[22]), "=r"((r)[23]), \
          "=r"((r)[24]), "=r"((r)[25]), "=r"((r)[26]), "=r"((r)[27]), \
          "=r"((r)[28]), "=r"((r)[29]), "=r"((r)[30]), "=r"((r)[31]) \
        : "r"(ta))

static constexpr uint64_t SMEM_DESC_BASE_SW128 =
    (uint64_t(2) << 61) | (uint64_t(1) << 46) | (uint64_t(64) << 32) | (uint64_t(1) << 16);
__device__ __forceinline__ uint64_t make_desc(uint32_t addr) {
    return SMEM_DESC_BASE_SW128 | ((uint64_t)(addr >> 4) & 0x3FFF);
}
// idesc: dtype=F32, atype=btype=BF16, N=128, M=128 (two-half dispatch)
#define IDESC_H 0x8200490u

#if HAS_TCGEN05
__device__ __forceinline__ void mma_f16_ss(uint32_t d, uint64_t ad, uint64_t bd,
                                           uint32_t idesc, uint32_t en) {
    asm volatile(
        "{\n\t.reg .pred p;\n\t"
        "setp.ne.u32 p, %5, 0;\n\t"
        "tcgen05.mma.cta_group::1.kind::f16 [%0], %1, %2, %3, {%4, %4, %4, %4}, p;\n\t}"
        :: "r"(d), "l"(ad), "l"(bd), "r"(idesc), "r"(0u), "r"(en) : "memory");
}
__device__ __forceinline__ void bulk_cp(uint32_t dst, const void* src, uint32_t bytes,
                                        uint32_t mb) {
    asm volatile(
        "cp.async.bulk.shared::cta.global.mbarrier::complete_tx::bytes [%0], [%1], %2, [%3];"
        :: "r"(dst), "l"(src), "r"(bytes), "r"(mb) : "memory");
}
#endif

__device__ __forceinline__ float warp_red(float v) {
    #pragma unroll
    for (int o = 16; o; o >>= 1) v += __shfl_xor_sync(0xffffffffu, v, o);
    return v;
}
// packed pair convert: res = bf16(a) | bf16(b)<<16
#define CVT2(res, a_, b_) \
    asm("cvt.rn.bf16x2.f32 %0, %1, %2;" : "=r"(res) : "f"(b_), "f"(a_))

// convert float4 -> packed {hi01, hi23, lo01, lo23}
__device__ __forceinline__ uint4 split_pack(float4 v) {
    uint4 pk;
    CVT2(pk.x, v.x, v.y);
    CVT2(pk.y, v.z, v.w);
    float h0 = __uint_as_float(pk.x << 16);
    float h1 = __uint_as_float(pk.x & 0xFFFF0000u);
    float h2 = __uint_as_float(pk.y << 16);
    float h3 = __uint_as_float(pk.y & 0xFFFF0000u);
    CVT2(pk.z, v.x - h0, v.y - h1);
    CVT2(pk.w, v.z - h2, v.w - h3);
    return pk;
}

// ---------------- kernel bodies (device functions for fusion) ----------------
__device__ void body_prep_w(int blk, const float* __restrict__ W, int K,
                            unsigned char* __restrict__ hi, unsigned char* __restrict__ lo) {
    int idx = blk * 256 + threadIdx.x;
    if (idx >= K * 256) return;
    int k = idx >> 8, n = idx & 255;
    float v = W[idx];
    __nv_bfloat16 h = __float2bfloat16_rn(v);
    __nv_bfloat16 l = __float2bfloat16_rn(v - __bfloat162float(h));
    int kt = k >> 6, kk = k & 63;
    uint32_t off = (uint32_t)(n * 128 + kk * 2);
    off ^= ((off >> 3) & 0x70);
    size_t base = (size_t)kt * 32768 + off;
    *(__nv_bfloat16*)(hi + base) = h;
    *(__nv_bfloat16*)(lo + base) = l;
}

__device__ void body_rel(int blk, const float* __restrict__ claim, const float* __restrict__ x,
                         const int* __restrict__ batch, float* __restrict__ rel,
                         int* __restrict__ cnt) {
    int warp = (blk * 256 + threadIdx.x) >> 5;
    int lane = threadIdx.x & 31;
    if (warp >= N_NODES) return;
    int b = batch[warp];
    const float4* ce = (const float4*)(claim + (size_t)b * D_IN);
    const float4* xv = (const float4*)(x + (size_t)warp * D_IN);
    float dot = 0.f, nc = 0.f, nx = 0.f;
    #pragma unroll
    for (int k = lane; k < D_IN / 4; k += 32) {
        float4 c = ce[k], v = xv[k];
        dot += c.x * v.x + c.y * v.y + c.z * v.z + c.w * v.w;
        nc  += c.x * c.x + c.y * c.y + c.z * c.z + c.w * c.w;
        nx  += v.x * v.x + v.y * v.y + v.z * v.z + v.w * v.w;
    }
    dot = warp_red(dot); nc = warp_red(nc); nx = warp_red(nx);
    if (lane == 0) {
        float nrm = sqrtf(nc) * sqrtf(nx);
        rel[warp] = dot / fmaxf(nrm, EPS_COS);
        atomicAdd(&cnt[b], 1);
    }
}

__device__ void body_hist(int blk, const int* __restrict__ ei, int* __restrict__ dcnt) {
    int i = blk * 256 + threadIdx.x;
    if (i >= E_TOT) return;
    int d = (i < N_EDGES) ? ei[N_EDGES + i] : (i - N_EDGES);
    atomicAdd(&dcnt[d], 1);
}

__device__ void body_fill(int blk, const int* __restrict__ ei, int* __restrict__ wr,
                          int* __restrict__ srcid) {
    int i = blk * 256 + threadIdx.x;
    if (i >= E_TOT) return;
    int s, d;
    if (i < N_EDGES) { s = ei[i]; d = ei[N_EDGES + i]; }
    else { s = d = i - N_EDGES; }
    int pos = atomicAdd(&wr[d], 1);
    srcid[pos] = s;
}

// ---- fused independent kernels (block-range dispatch) ----
#define NODE_BLKS  ((N_NODES + 255) / 256)
#define EDGE_BLKS  ((E_TOT + 255) / 256)
#define WNODE_BLKS ((N_NODES * 32 + 255) / 256)
#define PREP1_BLKS ((D_IN * 256 + 255) / 256)
#define PREP2_BLKS ((D_HID * 256 + 255) / 256)

__global__ void k_misc1(const float* claim, const float* x, const int* batch,
                        float* rel, int* cnt, const int* ei, int* dcnt,
                        const float* W1, unsigned char* w1h, unsigned char* w1l) {
    int b = blockIdx.x;
    if (b < WNODE_BLKS) { body_rel(b, claim, x, batch, rel, cnt); return; }
    b -= WNODE_BLKS;
    if (b < EDGE_BLKS) { body_hist(b, ei, dcnt); return; }
    b -= EDGE_BLKS;
    body_prep_w(b, W1, D_IN, w1h, w1l);
}
__global__ void k_misc2(const int* ei, int* wr, int* srcid,
                        const float* W2, unsigned char* w2h, unsigned char* w2l) {
    int b = blockIdx.x;
    if (b < EDGE_BLKS) { body_fill(b, ei, wr, srcid); return; }
    b -= EDGE_BLKS;
    body_prep_w(b, W2, D_HID, w2h, w2l);
}

// -------- tcgen05 GEMM: K=64, 256 thr, occ=2, B in two pipelined N-halves ----
#define SM_TPTR 0
#define SM_MBAR 8
#define SM_MBT0 16
#define SM_MBT1 24
#define SM_ASV  1024
#define SM_ADV  2048
#define SM_AH   3072
#define SM_AL   (SM_AH + 16384)
#define SM_BH   (SM_AL + 16384)
#define SM_BL   (SM_BH + 32768)
#define SM_SZ   (SM_BL + 32768)

__global__ __launch_bounds__(256, 2) void k_gemm_tc(
    const float* __restrict__ A, int K,
    const unsigned char* __restrict__ Bh, const unsigned char* __restrict__ Bl,
    float* __restrict__ C,
    const float* __restrict__ rowscale,
    const float* __restrict__ colsc, const float* __restrict__ colsh,
    const float* __restrict__ a_s, const float* __restrict__ a_d,
    float* __restrict__ as_out, float* __restrict__ ad_out, int M)
{
#if HAS_TCGEN05
    extern __shared__ char smem[];
    uint32_t sb = smem_to_u32(smem);
    int tid = threadIdx.x, wid = tid >> 5, lane = tid & 31;
    int m0 = blockIdx.x * 128;

    if (tid == 0) {
        MBARRIER_INIT(sb + SM_MBAR, 1);
        MBARRIER_INIT(sb + SM_MBT0, 1);
        MBARRIER_INIT(sb + SM_MBT1, 1);
    }
    if (wid == 0) TCGEN05_ALLOC(sb + SM_TPTR, 256);
    float* sAS = (float*)(smem + SM_ASV);
    float* sAD = (float*)(smem + SM_ADV);
    if (tid < 256) { sAS[tid] = a_s[tid]; sAD[tid] = a_d[tid]; }
    __syncthreads();
    uint32_t tmem;
    asm volatile("ld.shared.b32 %0, [%1];" : "=r"(tmem) : "r"(sb + SM_TPTR));
    if (wid == 0) TCGEN05_RELINQ();

    const uint64_t aH = make_desc(sb + SM_AH);
    const uint64_t aL = make_desc(sb + SM_AL);
    const uint64_t bH = make_desc(sb + SM_BH);
    const uint64_t bL = make_desc(sb + SM_BL);

    int rbase = tid >> 4;        // 0..15
    int cq = (tid & 15) << 2;    // 0,4,...,60
    int ph = 0, ph_t = 0;
    const int nk = K >> 6;

    float s_row[8];
    #pragma unroll
    for (int i = 0; i < 8; i++) {
        int gr = m0 + i * 16 + rbase;
        s_row[i] = (rowscale && gr < M) ? rowscale[gr] : 1.0f;
    }
    uint32_t so[8];
    #pragma unroll
    for (int i = 0; i < 8; i++) {
        uint32_t off = (uint32_t)((i * 16 + rbase) * 128 + cq * 2);
        so[i] = off ^ ((off >> 3) & 0x70);
    }

    auto convert_tile = [&](int kt, uint4* pk) {
        int k0 = kt << 6;
        float4 csc = make_float4(1.f, 1.f, 1.f, 1.f);
        float4 csh = make_float4(0.f, 0.f, 0.f, 0.f);
        if (colsc) {
            csc = *(const float4*)(colsc + k0 + cq);
            csh = *(const float4*)(colsh + k0 + cq);
        }
        float4 va[8];
        #pragma unroll
        for (int i = 0; i < 8; i++) {
            int gr = m0 + i * 16 + rbase;
            va[i] = (gr < M) ? *(const float4*)(A + (size_t)gr * K + k0 + cq)
                             : make_float4(0.f, 0.f, 0.f, 0.f);
        }
        #pragma unroll
        for (int i = 0; i < 8; i++) {
            float4 v = va[i];
            float sc = s_row[i];
            v.x *= sc; v.y *= sc; v.z *= sc; v.w *= sc;
            if (colsc) {
                v.x = fmaxf(v.x * csc.x + csh.x, 0.f);
                v.y = fmaxf(v.y * csc.y + csh.y, 0.f);
                v.z = fmaxf(v.z * csc.z + csh.z, 0.f);
                v.w = fmaxf(v.w * csc.w + csh.w, 0.f);
            }
            pk[i] = split_pack(v);
        }
    };

    uint4 pk[8];
    convert_tile(0, pk);

    for (int kt = 0; kt < nk; kt++) {
        if (kt) { MBARRIER_WAIT_PARITY(sb + SM_MBAR, ph); ph ^= 1; }

        // B copies split into N-halves: half0 = rows 0..127 (first 16KB of
        // each image tile), half1 = rows 128..255. MMAs for half0 start as
        // soon as half0 lands, overlapping half1's copy.
        if (tid == 0) {
            const unsigned char* bh = Bh + (size_t)kt * 32768;
            const unsigned char* bl = Bl + (size_t)kt * 32768;
            MBARRIER_EXPECT_TX(sb + SM_MBT0, 32768u);
            bulk_cp(sb + SM_BH, bh, 16384u, sb + SM_MBT0);
            bulk_cp(sb + SM_BL, bl, 16384u, sb + SM_MBT0);
            MBARRIER_EXPECT_TX(sb + SM_MBT1, 32768u);
            bulk_cp(sb + SM_BH + 16384, bh + 16384, 16384u, sb + SM_MBT1);
            bulk_cp(sb + SM_BL + 16384, bl + 16384, 16384u, sb + SM_MBT1);
        }
        // ---- STS of pre-converted tile ----
        #pragma unroll
        for (int i = 0; i < 8; i++) {
            *(uint2*)(smem + SM_AH + so[i]) = make_uint2(pk[i].x, pk[i].y);
            *(uint2*)(smem + SM_AL + so[i]) = make_uint2(pk[i].z, pk[i].w);
        }
        FENCE_ASYNC_SHARED();
        __syncthreads();
        // ---- MMAs: two N=128 halves, pipelined against B copies ----
        if (wid == 0) {
            MBARRIER_WAIT_PARITY(sb + SM_MBT0, ph_t);
            if (elect_one_pred()) {
                #pragma unroll
                for (int sp = 0; sp < 3; sp++) {
                    uint64_t ad = (sp == 2) ? aL : aH;
                    uint64_t bd = (sp == 1) ? bL : bH;
                    #pragma unroll
                    for (int c = 0; c < 4; c++) {
                        uint32_t en = (kt == 0 && sp == 0 && c == 0) ? 0u : 1u;
                        mma_f16_ss(tmem, ad + c * 2, bd + c * 2, IDESC_H, en);
                    }
                }
            }
            MBARRIER_WAIT_PARITY(sb + SM_MBT1, ph_t);
            if (elect_one_pred()) {
                #pragma unroll
                for (int sp = 0; sp < 3; sp++) {
                    uint64_t ad = (sp == 2) ? aL : aH;
                    uint64_t bd = ((sp == 1) ? bL : bH) + 1024;
                    #pragma unroll
                    for (int c = 0; c < 4; c++) {
                        uint32_t en = (kt == 0 && sp == 0 && c == 0) ? 0u : 1u;
                        mma_f16_ss(tmem + 128, ad + c * 2, bd + c * 2, IDESC_H, en);
                    }
                }
                TCGEN05_COMMIT(sb + SM_MBAR);
            }
        }
        ph_t ^= 1;
        // ---- convert tile kt+1 while MMA(kt) drains ----
        if (kt + 1 < nk) convert_tile(kt + 1, pk);
    }
    MBARRIER_WAIT_PARITY(sb + SM_MBAR, ph);
    TCGEN05_FENCE_AFTER();

    if (wid < 4) {
        int row = m0 + wid * 32 + lane;
        float s_acc = 0.f, d_acc = 0.f;
        #pragma unroll
        for (int j = 0; j < 8; j++) {
            uint32_t r[32];
            TCGEN05_LD_X32(r, tmem + j * 32);
            TCGEN05_WAIT_LD();
            #pragma unroll
            for (int q = 0; q < 32; q++) {
                float f = __uint_as_float(r[q]);
                s_acc += f * sAS[j * 32 + q];
                d_acc += f * sAD[j * 32 + q];
            }
            if (row < M) {
                float4* dst = (float4*)(C + (size_t)row * D_HID + j * 32);
                #pragma unroll
                for (int q = 0; q < 8; q++)
                    dst[q] = make_float4(__uint_as_float(r[q * 4 + 0]), __uint_as_float(r[q * 4 + 1]),
                                         __uint_as_float(r[q * 4 + 2]), __uint_as_float(r[q * 4 + 3]));
            }
        }
        if (row < M) { as_out[row] = s_acc; ad_out[row] = d_acc; }
        TCGEN05_FENCE_BEFORE();
    }
    __syncthreads();
    if (tid == 0) {
        asm volatile("mbarrier.inval.shared.b64 [%0];" :: "r"(sb + SM_MBAR) : "memory");
        asm volatile("mbarrier.inval.shared.b64 [%0];" :: "r"(sb + SM_MBT0) : "memory");
        asm volatile("mbarrier.inval.shared.b64 [%0];" :: "r"(sb + SM_MBT1) : "memory");
    }
    __syncthreads();
    if (wid == 0) TCGEN05_DEALLOC(tmem, 256);
#else
    // Correct scalar fallback for the non-arch-specific PTX pass.
    int tid = threadIdx.x;
    if (tid >= 128) return;
    int gr = blockIdx.x * 128 + tid;
    if (gr >= M) return;
    float rs = rowscale ? rowscale[gr] : 1.0f;
    float s_acc = 0.f, d_acc = 0.f;
    for (int n = 0; n < 256; n++) {
        float acc = 0.f;
        for (int k = 0; k < K; k++) {
            int kt = k >> 6, kk = k & 63;
            uint32_t off = (uint32_t)(n * 128 + kk * 2);
            off ^= ((off >> 3) & 0x70);
            float w = __bfloat162float(*(const __nv_bfloat16*)(Bh + (size_t)kt * 32768 + off))
                    + __bfloat162float(*(const __nv_bfloat16*)(Bl + (size_t)kt * 32768 + off));
            float a = A[(size_t)gr * K + k] * rs;
            if (colsc) a = fmaxf(a * colsc[k] + colsh[k], 0.f);
            acc += a * w;
        }
        C[(size_t)gr * 256 + n] = acc;
        s_acc += acc * a_s[n];
        d_acc += acc * a_d[n];
    }
    as_out[gr] = s_acc; ad_out[gr] = d_acc;
#endif
}

// ---------------- zero/init (single launch) ----------------
__global__ void k_zero_all(float* bnsum, float* bnsq, float* pool, int* cnt, int* dcnt) {
    int i = blockIdx.x * blockDim.x + threadIdx.x;
    if (i < N_NODES) dcnt[i] = 0;
    if (i < N_GRAPHS * D_HID) pool[i] = 0.0f;
    if (i < D_HID) { bnsum[i] = 0.0f; bnsq[i] = 0.0f; }
    if (i < N_GRAPHS) cnt[i] = 0;
}

// ---------------- CSR scan ----------------
__global__ __launch_bounds__(1024) void k_scan(const int* __restrict__ dcnt,
                                               int* __restrict__ rowoff,
                                               int* __restrict__ wr) {
    __shared__ int wsum[32];
    int t = threadIdx.x;
    int lane = t & 31, w = t >> 5;
    const int CH = (N_NODES + 1023) / 1024;   // 49
    int lo = t * CH, hi = min(lo + CH, N_NODES);
    int s = 0;
    for (int i = lo; i < hi; i++) s += dcnt[i];
    int inc = s;
    #pragma unroll
    for (int o = 1; o < 32; o <<= 1) {
        int v = __shfl_up_sync(0xffffffffu, inc, o);
        if (lane >= o) inc += v;
    }
    if (lane == 31) wsum[w] = inc;
    __syncthreads();
    if (w == 0) {
        int v = (lane < 32) ? wsum[lane] : 0;
        int wi = v;
        #pragma unroll
        for (int o = 1; o < 32; o <<= 1) {
            int u = __shfl_up_sync(0xffffffffu, wi, o);
            if (lane >= o) wi += u;
        }
        wsum[lane] = wi - v;   // exclusive
        if (lane == 31) rowoff[N_NODES] = wi;
    }
    __syncthreads();
    int run = wsum[w] + inc - s;
    for (int i = lo; i < hi; i++) {
        rowoff[i] = run; wr[i] = run;
        run += dcnt[i];
    }
}

// ---- score helper: attn numerator for edge (s -> d), no max-shift ----
__device__ __forceinline__ float edge_ex(const float* __restrict__ as, float add, int s) {
    float e = __ldg(as + s) + add;
    e = (e > 0.f) ? e : NEG_SLOPE * e;
    return __expf(e);
}

// ------- fused GAT edge phase (layer 1): softmax + CSR aggregation -------
__global__ void k_agg_fused(const float* __restrict__ h, float* __restrict__ agg,
                            const int* __restrict__ rowoff, const int* __restrict__ srcid,
                            const float* __restrict__ as, const float* __restrict__ ad) {
    int d = (int)(((size_t)blockIdx.x * blockDim.x + threadIdx.x) >> 5);
    int lane = threadIdx.x & 31;
    if (d >= N_NODES) return;
    int beg = rowoff[d], end = rowoff[d + 1];
    float add = ad[d];
    float part = 0.f;
    for (int i = beg + lane; i < end; i += 32)
        part += edge_ex(as, add, srcid[i]);
    float invden = __frcp_rn(warp_red(part));
    float4 a0 = make_float4(0.f, 0.f, 0.f, 0.f);
    float4 a1 = make_float4(0.f, 0.f, 0.f, 0.f);
    for (int i = beg; i < end; i++) {
        int s = srcid[i];
        float attn = edge_ex(as, add, s) * invden;
        const float4* hs = (const float4*)(h + (size_t)s * D_HID);
        float4 v0 = hs[lane], v1 = hs[lane + 32];
        a0.x += attn * v0.x; a0.y += attn * v0.y; a0.z += attn * v0.z; a0.w += attn * v0.w;
        a1.x += attn * v1.x; a1.y += attn * v1.y; a1.z += attn * v1.z; a1.w += attn * v1.w;
    }
    float4* od = (float4*)(agg + (size_t)d * D_HID);
    od[lane] = a0;
    od[lane + 32] = a1;
}

// ------- fused edge phase (layer 2): softmax + agg + relu(+b2) + mean-pool -------
__global__ void k_agg_pool_fused(const float* __restrict__ h,
                                 const int* __restrict__ rowoff, const int* __restrict__ srcid,
                                 const float* __restrict__ as, const float* __restrict__ ad,
                                 const float* __restrict__ b2,
                                 const int* __restrict__ batch,
                                 float* __restrict__ pool) {
    int d = (int)(((size_t)blockIdx.x * blockDim.x + threadIdx.x) >> 5);
    int lane = threadIdx.x & 31;
    if (d >= N_NODES) return;
    int beg = rowoff[d], end = rowoff[d + 1];
    float add = ad[d];
    float part = 0.f;
    for (int i = beg + lane; i < end; i += 32)
        part += edge_ex(as, add, srcid[i]);
    float invden = __frcp_rn(warp_red(part));
    float4 a0 = make_float4(0.f, 0.f, 0.f, 0.f);
    float4 a1 = make_float4(0.f, 0.f, 0.f, 0.f);
    for (int i = beg; i < end; i++) {
        int s = srcid[i];
        float attn = edge_ex(as, add, s) * invden;
        const float4* hs = (const float4*)(h + (size_t)s * D_HID);
        float4 v0 = hs[lane], v1 = hs[lane + 32];
        a0.x += attn * v0.x; a0.y += attn * v0.y; a0.z += attn * v0.z; a0.w += attn * v0.w;
        a1.x += attn * v1.x; a1.y += attn * v1.y; a1.z += attn * v1.z; a1.w += attn * v1.w;
    }
    float4 b0 = ((const float4*)b2)[lane];
    float4 b1 = ((const float4*)b2)[lane + 32];
    a0.x = fmaxf(a0.x + b0.x, 0.f); a0.y = fmaxf(a0.y + b0.y, 0.f);
    a0.z = fmaxf(a0.z + b0.z, 0.f); a0.w = fmaxf(a0.w + b0.w, 0.f);
    a1.x = fmaxf(a1.x + b1.x, 0.f); a1.y = fmaxf(a1.y + b1.y, 0.f);
    a1.z = fmaxf(a1.z + b1.z, 0.f); a1.w = fmaxf(a1.w + b1.w, 0.f);
    int g = batch[d];
    float4* pg = (float4*)(pool + (size_t)g * D_HID);
    asm volatile("red.global.add.v4.f32 [%0], {%1,%2,%3,%4};"
                 :: "l"(pg + lane), "f"(a0.x), "f"(a0.y), "f"(a0.z), "f"(a0.w) : "memory");
    asm volatile("red.global.add.v4.f32 [%0], {%1,%2,%3,%4};"
                 :: "l"(pg + lane + 32), "f"(a1.x), "f"(a1.y), "f"(a1.z), "f"(a1.w) : "memory");
}

// ---------------- BatchNorm stats ----------------
#define ROWS_PER_BLK 64
__global__ void k_bnstats(const float* __restrict__ h, float* __restrict__ bsum,
                          float* __restrict__ bsq) {
    int col = threadIdx.x;
    int r0 = blockIdx.x * ROWS_PER_BLK;
    int r1 = min(r0 + ROWS_PER_BLK, N_NODES);
    float s = 0.f, q = 0.f;
    for (int r = r0; r < r1; r++) {
        float v = h[(size_t)r * D_HID + col];
        s += v; q += v * v;
    }
    atomicAdd(&bsum[col], s);
    atomicAdd(&bsq[col], q);
}

// ---------------- BN finalize: per-column scale/shift ----------------
__global__ void k_bnfin(const float* __restrict__ bsum, const float* __restrict__ bsq,
                        const float* __restrict__ gamma, const float* __restrict__ beta,
                        float* __restrict__ sc, float* __restrict__ sh) {
    int col = threadIdx.x;
    float mu = bsum[col] * (1.0f / N_NODES);
    float var = bsq[col] * (1.0f / N_NODES) - mu * mu;
    float s = gamma[col] * rsqrtf(var + EPS_BN);
    sc[col] = s;
    sh[col] = beta[col] - mu * s;
}

// ---------------- classifier ----------------
__global__ void k_clf(const float* __restrict__ pool, const int* __restrict__ cnt,
                      const float* __restrict__ claim, const float* __restrict__ W,
                      const float* __restrict__ bias, float* __restrict__ out) {
    __shared__ float red[256];
    int b = blockIdx.x;
    int t = threadIdx.x;
    float c = fmaxf((float)cnt[b], 1.0f);
    float part = (pool[b * D_HID + t] / c) * W[t];
    #pragma unroll
    for (int j = 0; j < 3; j++) {
        int k = t + j * 256;
        part += claim[(size_t)b * D_IN + k] * W[D_HID + k];
    }
    red[t] = part;
    __syncthreads();
    #pragma unroll
    for (int o = 128; o; o >>= 1) {
        if (t < o) red[t] += red[t + o];
        __syncthreads();
    }
    if (t == 0) out[b] = red[0] + bias[0];
}

// ---------------- host launcher ----------------
extern "C" void kernel_launch(void* const* d_in, const int* in_sizes, int n_in,
                              void* d_out, int out_size) {
    const float* claim   = (const float*)d_in[0];
    const float* x       = (const float*)d_in[1];
    const int*   ei      = (const int*)d_in[2];
    const int*   batch   = (const int*)d_in[3];
    const float* W1      = (const float*)d_in[4];
    const float* a_src1  = (const float*)d_in[5];
    const float* a_dst1  = (const float*)d_in[6];
    // d_in[7] = b1 : provably no-op through training-mode BatchNorm
    const float* W2      = (const float*)d_in[8];
    const float* a_src2  = (const float*)d_in[9];
    const float* a_dst2  = (const float*)d_in[10];
    const float* b2      = (const float*)d_in[11];
    const float* gamma   = (const float*)d_in[12];
    const float* beta    = (const float*)d_in[13];
    const float* clfW    = (const float*)d_in[14];
    const float* clfb    = (const float*)d_in[15];
    float* out = (float*)d_out;

    float *p_rel, *p_A, *p_B, *p_as, *p_ad, *p_bnsum, *p_bnsq, *p_bnsc, *p_bnsh, *p_pool;
    int *p_cnt, *p_dcnt, *p_rowoff, *p_wr, *p_srcid;
    unsigned char *p_w1h, *p_w1l, *p_w2h, *p_w2l;
    cudaGetSymbolAddress((void**)&p_rel, g_rel);
    cudaGetSymbolAddress((void**)&p_A, g_bufA);
    cudaGetSymbolAddress((void**)&p_B, g_bufB);
    cudaGetSymbolAddress((void**)&p_as, g_as);
    cudaGetSymbolAddress((void**)&p_ad, g_ad);
    cudaGetSymbolAddress((void**)&p_bnsum, g_bnsum);
    cudaGetSymbolAddress((void**)&p_bnsq, g_bnsq);
    cudaGetSymbolAddress((void**)&p_bnsc, g_bnsc);
    cudaGetSymbolAddress((void**)&p_bnsh, g_bnsh);
    cudaGetSymbolAddress((void**)&p_pool, g_pool);
    cudaGetSymbolAddress((void**)&p_cnt, g_cnt);
    cudaGetSymbolAddress((void**)&p_dcnt, g_dcnt);
    cudaGetSymbolAddress((void**)&p_rowoff, g_rowoff);
    cudaGetSymbolAddress((void**)&p_wr, g_wr);
    cudaGetSymbolAddress((void**)&p_srcid, g_srcid);
    cudaGetSymbolAddress((void**)&p_w1h, g_w1h);
    cudaGetSymbolAddress((void**)&p_w1l, g_w1l);
    cudaGetSymbolAddress((void**)&p_w2h, g_w2h);
    cudaGetSymbolAddress((void**)&p_w2l, g_w2l);

    cudaFuncSetAttribute(k_gemm_tc, cudaFuncAttributeMaxDynamicSharedMemorySize, SM_SZ);

    const int chunkBlocks = (N_NODES + ROWS_PER_BLK - 1) / ROWS_PER_BLK;
    const int gemmBlocks = (N_NODES + 127) / 128;

    // launch order: GEMM1 stays the 4th launch (ncu captures #4).
    k_zero_all<<<NODE_BLKS, 256>>>(p_bnsum, p_bnsq, p_pool, p_cnt, p_dcnt);
    k_misc1<<<WNODE_BLKS + EDGE_BLKS + PREP1_BLKS, 256>>>(
        claim, x, batch, p_rel, p_cnt, ei, p_dcnt, W1, p_w1h, p_w1l);
    k_scan<<<1, 1024>>>(p_dcnt, p_rowoff, p_wr);
    k_gemm_tc<<<gemmBlocks, 256, SM_SZ>>>(x, D_IN, p_w1h, p_w1l, p_A,
                                          p_rel, nullptr, nullptr,
                                          a_src1, a_dst1, p_as, p_ad, N_NODES);
    k_misc2<<<EDGE_BLKS + PREP2_BLKS, 256>>>(ei, p_wr, p_srcid, W2, p_w2h, p_w2l);

    // ---- layer 1: fused softmax + aggregation ----
    k_agg_fused<<<WNODE_BLKS, 256>>>(p_A, p_B, p_rowoff, p_srcid, p_as, p_ad);

    // ---- BN stats + finalize (apply fused into GEMM2's A-loader) ----
    k_bnstats<<<chunkBlocks, 256>>>(p_B, p_bnsum, p_bnsq);
    k_bnfin<<<1, 256>>>(p_bnsum, p_bnsq, gamma, beta, p_bnsc, p_bnsh);

    // ---- layer 2: GEMM (BN+ReLU fused) + fused edge phase + pooling ----
    k_gemm_tc<<<gemmBlocks, 256, SM_SZ>>>(p_B, D_HID, p_w2h, p_w2l, p_A,
                                          nullptr, p_bnsc, p_bnsh,
                                          a_src2, a_dst2, p_as, p_ad, N_NODES);
    k_agg_pool_fused<<<WNODE_BLKS, 256>>>(p_A, p_rowoff, p_srcid, p_as, p_ad,
                                          b2, batch, p_pool);

    // ---- classifier ----
    k_clf<<<N_GRAPHS, 256>>>(p_pool, p_cnt, claim, clfW, clfb, out);
}